// round 9
// baseline (speedup 1.0000x reference)
#include <cuda_runtime.h>
#include <cuda_bf16.h>
#include <cstdint>

#define NMAX 100000
#define EMAX 1600000
#define DIN  256
#define F    64
#define C2   128

// ---------------- scratch (device globals: allocation-free rule) ----------------
__device__ float  g_ZH[(size_t)NMAX * C2];   // H = leaky(X@W) rows
__device__ float4 g_Q[NMAX];                 // per-node score scalars, pre-scaled by 1/||a||
__device__ float  g_w[6 * F];                // folded a-vector combos
__device__ float  g_scal[4];                 // inv_norm_high, inv_norm_low, theta_high, theta_low
__device__ int    g_deg[NMAX + 4];
__device__ int    g_rs[NMAX + 4];            // CSR row start (exclusive prefix of deg)
__device__ int    g_cur[NMAX + 4];           // fill cursors
__device__ int    g_csr[EMAX];               // dst indices grouped by src
// Pre-split, pre-transposed B = [Wh|Wl]: [128 n][256 k] bf16 hi/lo images (L2-hot).
__device__ __align__(16) __nv_bfloat16 g_Bt_h[128 * 256];
__device__ __align__(16) __nv_bfloat16 g_Bt_l[128 * 256];

__device__ __forceinline__ float leaky(float x) { return fmaxf(x, 0.2f * x); }

__device__ __forceinline__ uint32_t smem_u32(const void* p) {
    uint32_t a;
    asm("{ .reg .u64 t; cvta.to.shared.u64 t, %1; cvt.u32.u64 %0, t; }" : "=r"(a) : "l"(p));
    return a;
}

__device__ __forceinline__ void split_bf16(float x, __nv_bfloat16& hi, __nv_bfloat16& lo) {
    hi = __float2bfloat16(x);
    lo = __float2bfloat16(x - __bfloat162float(hi));
}

#define LDMX4(r0, r1, r2, r3, addr) \
    asm volatile("ldmatrix.sync.aligned.m8n8.x4.shared.b16 {%0,%1,%2,%3}, [%4];" \
                 : "=r"(r0), "=r"(r1), "=r"(r2), "=r"(r3) : "r"(addr))

#define MMA16816(d, a, b0, b1) \
    asm volatile("mma.sync.aligned.m16n8k16.row.col.f32.bf16.bf16.f32 " \
                 "{%0,%1,%2,%3}, {%4,%5,%6,%7}, {%8,%9}, {%0,%1,%2,%3};" \
                 : "+f"((d)[0]), "+f"((d)[1]), "+f"((d)[2]), "+f"((d)[3]) \
                 : "r"((a)[0]), "r"((a)[1]), "r"((a)[2]), "r"((a)[3]), "r"(b0), "r"(b1))

// ---------------- K0: setup (prep scalars/weights + B images + zero deg) ----------------
__global__ void setup_kernel(const float* __restrict__ Wh, const float* __restrict__ Wl,
                             const float* __restrict__ ah, const float* __restrict__ al,
                             const float* __restrict__ ch, const float* __restrict__ cl) {
    int t = threadIdx.x;
    int e = blockIdx.x * 256 + t;        // 0..32767 over 128 blocks

    // block 0: norms, thetas, folded weight vectors
    if (blockIdx.x == 0) {
        __shared__ float sh[256], sl[256];
        float vh = ah[t], vl = al[t];
        sh[t] = vh * vh; sl[t] = vl * vl;
        __syncthreads();
        for (int o = 128; o; o >>= 1) {
            if (t < o) { sh[t] += sh[t + o]; sl[t] += sl[t + o]; }
            __syncthreads();
        }
        if (t == 0) {
            g_scal[0] = 1.0f / sqrtf(sh[0]);
            g_scal[1] = 1.0f / sqrtf(sl[0]);
            float c = ch[0];
            g_scal[2] = (fminf(fmaxf(c + 3.0f, 0.0f), 6.0f) / 3.0f + 1e-6f) * 0.5f;
            c = cl[0];
            g_scal[3] = (fminf(fmaxf(c + 3.0f, 0.0f), 6.0f) / 3.0f + 1e-6f) * 0.5f;
        }
        if (t < F) {
            g_w[t]         = ah[t]     + ah[2*F+t] + ah[3*F+t];   // wh1
            g_w[F + t]     = ah[F+t]   + ah[2*F+t] - ah[3*F+t];   // wh2
            g_w[2*F + t]   = al[t];                                // vl1
            g_w[3*F + t]   = al[F+t];                              // vl2
            g_w[4*F + t]   = al[2*F+t] + al[3*F+t];                // vl3
            g_w[5*F + t]   = al[2*F+t] - al[3*F+t];                // vl4
        }
    }

    // all blocks: B split/transpose image
    {
        int n = e >> 8;
        int k = e & 255;
        float v = (n < 64) ? Wh[(size_t)k * F + n] : Wl[(size_t)k * F + (n - 64)];
        __nv_bfloat16 hi, lo;
        split_bf16(v, hi, lo);
        g_Bt_h[e] = hi;
        g_Bt_l[e] = lo;
    }

    // all blocks: zero degree array
    for (int i = e; i < NMAX + 4; i += 32768) g_deg[i] = 0;
}

// ---------------- CSR build ----------------
__global__ void count_kernel(const int* __restrict__ src, int E) {
    int i = blockIdx.x * blockDim.x + threadIdx.x;
    int stride = gridDim.x * blockDim.x;
    for (int e = i; e < E; e += stride) atomicAdd(&g_deg[__ldg(src + e)], 1);
}

// 1024 threads, contiguous chunks (multiple of 4), int4-vectorized both phases.
__global__ void scan_kernel(int N) {
    __shared__ int part[1024];
    int t = threadIdx.x;
    int Cc = (((N + 1023) >> 10) + 3) & ~3;
    int base = t * Cc;
    int s = 0;
    for (int i = 0; i < Cc; i += 4) {
        int idx = base + i;
        if (idx < N) {
            int4 v = *(const int4*)&g_deg[idx];   // padded; beyond-N entries are 0
            s += v.x + v.y + v.z + v.w;
        }
    }
    part[t] = s;
    __syncthreads();
    for (int o = 1; o < 1024; o <<= 1) {
        int v = (t >= o) ? part[t - o] : 0;
        __syncthreads();
        part[t] += v;
        __syncthreads();
    }
    int run = part[t] - s;
    for (int i = 0; i < Cc; i += 4) {
        int idx = base + i;
        if (idx < N) {
            int4 v = *(const int4*)&g_deg[idx];
            int4 r;
            r.x = run;
            r.y = r.x + v.x;
            r.z = r.y + v.y;
            r.w = r.z + v.z;
            run = r.w + v.w;
            *(int4*)&g_rs[idx]  = r;
            *(int4*)&g_cur[idx] = r;
        }
    }
}

__global__ void fill_kernel(const int* __restrict__ src, const int* __restrict__ dst, int E) {
    int i = blockIdx.x * blockDim.x + threadIdx.x;
    int stride = gridDim.x * blockDim.x;
    for (int e = i; e < E; e += stride) {
        int s = __ldg(src + e);
        int pos = atomicAdd(&g_cur[s], 1);
        g_csr[pos] = __ldg(dst + e);
    }
}

// ---------------- K1: HMMA split-bf16 GEMM (512 thr, warp=32x32) + fused leaky + Q ----------------
#define ASTRIDE 40   // bf16 elements per smem row (32 + 8 pad)

__global__ void __launch_bounds__(512) gemm_tc_kernel(const float* __restrict__ X, int N) {
    __shared__ __nv_bfloat16 As_h[128 * ASTRIDE];
    __shared__ __nv_bfloat16 As_l[128 * ASTRIDE];
    __shared__ __nv_bfloat16 Bs_h[128 * ASTRIDE];
    __shared__ __nv_bfloat16 Bs_l[128 * ASTRIDE];
    __shared__ float sW[6 * F];          // folded weight vectors
    __shared__ float sQH[2][128][4];     // high-half partial dots (warp_n 0,1)
    __shared__ float sQL[2][128][2];     // low-half partial dots (warp_n 2,3)

    int tid  = threadIdx.x;
    int wid  = tid >> 5;
    int lane = tid & 31;
    int brow = blockIdx.x * 128;
    int warp_m = wid & 3;      // 32-row slab
    int warp_n = wid >> 2;     // 32-col slab (0,1 = high; 2,3 = low)

    if (tid < 128) {
        sW[tid]       = g_w[tid];
        sW[tid + 128] = g_w[tid + 128];
        sW[tid + 256] = g_w[tid + 256];
    }

    float acc[2][4][4];
    #pragma unroll
    for (int mi = 0; mi < 2; mi++)
        #pragma unroll
        for (int ni = 0; ni < 4; ni++)
            #pragma unroll
            for (int q = 0; q < 4; q++) acc[mi][ni][q] = 0.f;

    uint32_t sbAH = smem_u32(As_h), sbAL = smem_u32(As_l);
    uint32_t sbBH = smem_u32(Bs_h), sbBL = smem_u32(Bs_l);

    int a_r = lane & 15, a_c = (lane >> 4) << 3;
    int b_r = lane & 7;
    int b_n = ((lane >> 4) & 1) << 3;
    int b_k = ((lane >> 3) & 1) << 3;

    // per-thread load indices (512 threads)
    int arow[2], ac4[2];
    #pragma unroll
    for (int i = 0; i < 2; i++) {
        int idx = tid + 512 * i;        // 1024 float4 slots of 128x32 fp32
        arow[i] = idx >> 3;
        ac4[i]  = (idx & 7) << 2;
    }
    int bn = tid >> 2;
    int bk = (tid & 3) << 3;

    float4 xa[2];
    uint4  pbh, pbl;

    #pragma unroll
    for (int i = 0; i < 2; i++) {
        int grow = brow + arow[i];
        xa[i] = (grow < N) ? *(const float4*)(X + (size_t)grow * DIN + ac4[i])
                           : make_float4(0.f, 0.f, 0.f, 0.f);
    }
    pbh = *(const uint4*)(g_Bt_h + (size_t)bn * 256 + bk);
    pbl = *(const uint4*)(g_Bt_l + (size_t)bn * 256 + bk);

    for (int chunk = 0; chunk < 8; chunk++) {
        __syncthreads();
        #pragma unroll
        for (int i = 0; i < 2; i++) {
            float4 v = xa[i];
            __nv_bfloat16 h0, h1, h2, h3, l0, l1, l2, l3;
            split_bf16(v.x, h0, l0); split_bf16(v.y, h1, l1);
            split_bf16(v.z, h2, l2); split_bf16(v.w, h3, l3);
            int o = arow[i] * ASTRIDE + ac4[i];
            __nv_bfloat162 p;
            p.x = h0; p.y = h1; *(__nv_bfloat162*)&As_h[o]     = p;
            p.x = h2; p.y = h3; *(__nv_bfloat162*)&As_h[o + 2] = p;
            p.x = l0; p.y = l1; *(__nv_bfloat162*)&As_l[o]     = p;
            p.x = l2; p.y = l3; *(__nv_bfloat162*)&As_l[o + 2] = p;
        }
        *(uint4*)&Bs_h[bn * ASTRIDE + bk] = pbh;
        *(uint4*)&Bs_l[bn * ASTRIDE + bk] = pbl;
        __syncthreads();

        if (chunk < 7) {
            int k0 = (chunk + 1) * 32;
            #pragma unroll
            for (int i = 0; i < 2; i++) {
                int grow = brow + arow[i];
                xa[i] = (grow < N) ? *(const float4*)(X + (size_t)grow * DIN + k0 + ac4[i])
                                   : make_float4(0.f, 0.f, 0.f, 0.f);
            }
            pbh = *(const uint4*)(g_Bt_h + (size_t)bn * 256 + k0 + bk);
            pbl = *(const uint4*)(g_Bt_l + (size_t)bn * 256 + k0 + bk);
        }

        #pragma unroll
        for (int ks = 0; ks < 2; ks++) {
            int k16 = ks * 16;
            uint32_t ah[2][4], al[2][4];
            #pragma unroll
            for (int mi = 0; mi < 2; mi++) {
                uint32_t aoff = ((warp_m * 32 + mi * 16 + a_r) * ASTRIDE + k16 + a_c) * 2;
                LDMX4(ah[mi][0], ah[mi][1], ah[mi][2], ah[mi][3], sbAH + aoff);
                LDMX4(al[mi][0], al[mi][1], al[mi][2], al[mi][3], sbAL + aoff);
            }
            #pragma unroll
            for (int np = 0; np < 2; np++) {
                uint32_t boff = ((warp_n * 32 + np * 16 + b_n + b_r) * ASTRIDE + k16 + b_k) * 2;
                uint32_t bh[4], bl[4];
                LDMX4(bh[0], bh[1], bh[2], bh[3], sbBH + boff);
                LDMX4(bl[0], bl[1], bl[2], bl[3], sbBL + boff);
                #pragma unroll
                for (int mi = 0; mi < 2; mi++) {
                    #pragma unroll
                    for (int h = 0; h < 2; h++) {
                        float* d = acc[mi][np * 2 + h];
                        MMA16816(d, ah[mi], bh[2 * h], bh[2 * h + 1]);
                        MMA16816(d, ah[mi], bl[2 * h], bl[2 * h + 1]);
                        MMA16816(d, al[mi], bh[2 * h], bh[2 * h + 1]);
                    }
                }
            }
        }
    }

    // --- Epilogue: leaky + store H + fused per-row score dots ---
    __syncthreads();
    int rq  = lane >> 2;
    int cq  = (lane & 3) << 1;
    bool hiw = warp_n < 2;
    float dots[2][2][4];
    #pragma unroll
    for (int mi = 0; mi < 2; mi++)
        #pragma unroll
        for (int rh = 0; rh < 2; rh++)
            #pragma unroll
            for (int q = 0; q < 4; q++) dots[mi][rh][q] = 0.f;

    #pragma unroll
    for (int mi = 0; mi < 2; mi++) {
        int r0 = brow + warp_m * 32 + mi * 16 + rq;
        #pragma unroll
        for (int ni = 0; ni < 4; ni++) {
            int c  = warp_n * 32 + ni * 8 + cq;          // global col 0..127
            int lc = hiw ? c : (c - 64);                 // col within the 64-col half
            float* d = acc[mi][ni];
            float h0 = leaky(d[0]), h1 = leaky(d[1]);
            float h2 = leaky(d[2]), h3 = leaky(d[3]);
            if (r0 < N)
                *(float2*)&g_ZH[(size_t)r0 * C2 + c] = make_float2(h0, h1);
            if (r0 + 8 < N)
                *(float2*)&g_ZH[(size_t)(r0 + 8) * C2 + c] = make_float2(h2, h3);
            if (hiw) {
                #pragma unroll
                for (int q = 0; q < 4; q++) {
                    float wa = sW[q * F + lc], wb = sW[q * F + lc + 1];
                    dots[mi][0][q] = fmaf(h0, wa, fmaf(h1, wb, dots[mi][0][q]));
                    dots[mi][1][q] = fmaf(h2, wa, fmaf(h3, wb, dots[mi][1][q]));
                }
            } else {
                #pragma unroll
                for (int q = 0; q < 2; q++) {
                    float wa = sW[(4 + q) * F + lc], wb = sW[(4 + q) * F + lc + 1];
                    dots[mi][0][q] = fmaf(h0, wa, fmaf(h1, wb, dots[mi][0][q]));
                    dots[mi][1][q] = fmaf(h2, wa, fmaf(h3, wb, dots[mi][1][q]));
                }
            }
        }
    }
    #pragma unroll
    for (int mi = 0; mi < 2; mi++)
        #pragma unroll
        for (int rh = 0; rh < 2; rh++)
            #pragma unroll
            for (int q = 0; q < 4; q++) {
                float v = dots[mi][rh][q];
                v += __shfl_xor_sync(0xffffffffu, v, 1);
                v += __shfl_xor_sync(0xffffffffu, v, 2);
                dots[mi][rh][q] = v;
            }
    if ((lane & 3) == 0) {
        #pragma unroll
        for (int mi = 0; mi < 2; mi++)
            #pragma unroll
            for (int rh = 0; rh < 2; rh++) {
                int row = warp_m * 32 + mi * 16 + rh * 8 + rq;
                if (hiw) {
                    sQH[warp_n][row][0] = dots[mi][rh][0];
                    sQH[warp_n][row][1] = dots[mi][rh][1];
                    sQH[warp_n][row][2] = dots[mi][rh][2];
                    sQH[warp_n][row][3] = dots[mi][rh][3];
                } else {
                    sQL[warp_n - 2][row][0] = dots[mi][rh][0];
                    sQL[warp_n - 2][row][1] = dots[mi][rh][1];
                }
            }
    }
    __syncthreads();
    if (tid < 128) {
        int grow = brow + tid;
        if (grow < N) {
            float inh = g_scal[0], inl = g_scal[1];
            g_Q[grow] = make_float4(
                (sQH[0][tid][0] + sQH[1][tid][0]) * inh,
                (sQH[0][tid][1] + sQH[1][tid][1]) * inh,
                (sQH[0][tid][2] + sQH[1][tid][2] + sQL[0][tid][0] + sQL[1][tid][0]) * inl,
                (sQH[0][tid][3] + sQH[1][tid][3] + sQL[0][tid][1] + sQL[1][tid][1]) * inl);
        }
    }
}

// ---------------- K3: CSR aggregation, warp per node, edge-parallel two-phase ----------------
__global__ void __launch_bounds__(256) agg_kernel(float* __restrict__ out, int N) {
    int gw   = (int)(((size_t)blockIdx.x * blockDim.x + threadIdx.x) >> 5);
    int lane = threadIdx.x & 31;
    if (gw >= N) return;
    float4 qs = g_Q[gw];
    int start = g_rs[gw];
    int end   = start + g_deg[gw];
    bool hi = lane < 16;
    float4 acc = make_float4(0.f, 0.f, 0.f, 0.f);
    float rsh = 0.f, rsl = 0.f;
    for (int base = start; base < end; base += 32) {
        int cnt = min(32, end - base);
        int   d_l  = 0;
        float eh_l = 0.f, el_l = 0.f;
        if (lane < cnt) {
            d_l = __ldg(&g_csr[base + lane]);
            float4 qd = __ldg(&g_Q[d_l]);
            float sch = qs.x + qd.y;
            float scl = qs.z + qd.w;
            eh_l = __expf(-fmaxf(sch, 0.2f * sch));
            el_l = __expf(-fmaxf(scl, 0.2f * scl));
        }
        rsh += eh_l;
        rsl += el_l;
        for (int j = 0; j < cnt; j++) {
            int   dj  = __shfl_sync(0xffffffffu, d_l, j);
            float ehj = __shfl_sync(0xffffffffu, eh_l, j);
            float elj = __shfl_sync(0xffffffffu, el_l, j);
            float4 hv = __ldg((const float4*)&g_ZH[(size_t)dj * C2 + lane * 4]);
            float ec = hi ? ehj : elj;
            acc.x = fmaf(hv.x, ec, acc.x);
            acc.y = fmaf(hv.y, ec, acc.y);
            acc.z = fmaf(hv.z, ec, acc.z);
            acc.w = fmaf(hv.w, ec, acc.w);
        }
    }
    #pragma unroll
    for (int o = 16; o; o >>= 1) {
        rsh += __shfl_xor_sync(0xffffffffu, rsh, o);
        rsl += __shfl_xor_sync(0xffffffffu, rsl, o);
    }
    float theta = hi ? g_scal[2] : g_scal[3];
    float inv = 1.0f / ((hi ? rsh : rsl) + theta);
    float4 v = make_float4(leaky(acc.x * inv), leaky(acc.y * inv),
                           leaky(acc.z * inv), leaky(acc.w * inv));
    *(float4*)(out + (size_t)gw * C2 + lane * 4) = v;
}

extern "C" void kernel_launch(void* const* d_in, const int* in_sizes, int n_in,
                              void* d_out, int out_size) {
    const float* X    = (const float*)d_in[0];
    const int*   edge = (const int*)d_in[1];
    const float* Wh   = (const float*)d_in[2];
    const float* Wl   = (const float*)d_in[3];
    const float* ah   = (const float*)d_in[4];
    const float* al   = (const float*)d_in[5];
    const float* ch   = (const float*)d_in[6];
    const float* cl   = (const float*)d_in[7];
    float* out = (float*)d_out;

    int N = in_sizes[0] / DIN;
    int E = in_sizes[1] / 2;

    setup_kernel<<<128, 256>>>(Wh, Wl, ah, al, ch, cl);
    count_kernel<<<2048, 256>>>(edge, E);
    scan_kernel<<<1, 1024>>>(N);
    fill_kernel<<<2048, 256>>>(edge, edge + E, E);
    gemm_tc_kernel<<<(N + 127) / 128, 512>>>(X, N);
    agg_kernel<<<(N * 32 + 255) / 256, 256>>>(out, N);
}

// round 10
// speedup vs baseline: 1.5124x; 1.5124x over previous
#include <cuda_runtime.h>
#include <cuda_bf16.h>
#include <cstdint>

#define NMAX 100000
#define EMAX 1600000
#define DIN  256
#define F    64
#define C2   128

// ---------------- scratch (device globals: allocation-free rule) ----------------
__device__ float  g_ZH[(size_t)NMAX * C2];   // H = leaky(X@W) rows
__device__ float4 g_Q[NMAX];                 // per-node score scalars, pre-scaled by 1/||a||
__device__ float  g_w[6 * F];                // folded a-vector combos
__device__ float  g_scal[4];                 // inv_norm_high, inv_norm_low, theta_high, theta_low
__device__ int    g_deg[NMAX + 4];
__device__ int    g_rs[NMAX + 4];            // CSR row start (exclusive prefix of deg)
__device__ int    g_cur[NMAX + 4];           // fill cursors
__device__ int    g_csr[EMAX];               // dst indices grouped by src
// Pre-split, pre-transposed B = [Wh|Wl]: [128 n][256 k] bf16 hi/lo images (L2-hot).
__device__ __align__(16) __nv_bfloat16 g_Bt_h[128 * 256];
__device__ __align__(16) __nv_bfloat16 g_Bt_l[128 * 256];

__device__ __forceinline__ float leaky(float x) { return fmaxf(x, 0.2f * x); }

__device__ __forceinline__ uint32_t smem_u32(const void* p) {
    uint32_t a;
    asm("{ .reg .u64 t; cvta.to.shared.u64 t, %1; cvt.u32.u64 %0, t; }" : "=r"(a) : "l"(p));
    return a;
}

__device__ __forceinline__ void split_bf16(float x, __nv_bfloat16& hi, __nv_bfloat16& lo) {
    hi = __float2bfloat16(x);
    lo = __float2bfloat16(x - __bfloat162float(hi));
}

#define LDMX4(r0, r1, r2, r3, addr) \
    asm volatile("ldmatrix.sync.aligned.m8n8.x4.shared.b16 {%0,%1,%2,%3}, [%4];" \
                 : "=r"(r0), "=r"(r1), "=r"(r2), "=r"(r3) : "r"(addr))

#define MMA16816(d, a, b0, b1) \
    asm volatile("mma.sync.aligned.m16n8k16.row.col.f32.bf16.bf16.f32 " \
                 "{%0,%1,%2,%3}, {%4,%5,%6,%7}, {%8,%9}, {%0,%1,%2,%3};" \
                 : "+f"((d)[0]), "+f"((d)[1]), "+f"((d)[2]), "+f"((d)[3]) \
                 : "r"((a)[0]), "r"((a)[1]), "r"((a)[2]), "r"((a)[3]), "r"(b0), "r"(b1))

// ---------------- K0: setup (prep scalars/weights + B images + zero deg) ----------------
__global__ void setup_kernel(const float* __restrict__ Wh, const float* __restrict__ Wl,
                             const float* __restrict__ ah, const float* __restrict__ al,
                             const float* __restrict__ ch, const float* __restrict__ cl) {
    int t = threadIdx.x;
    int e = blockIdx.x * 256 + t;        // 0..32767 over 128 blocks

    if (blockIdx.x == 0) {
        __shared__ float sh[256], sl[256];
        float vh = ah[t], vl = al[t];
        sh[t] = vh * vh; sl[t] = vl * vl;
        __syncthreads();
        for (int o = 128; o; o >>= 1) {
            if (t < o) { sh[t] += sh[t + o]; sl[t] += sl[t + o]; }
            __syncthreads();
        }
        if (t == 0) {
            g_scal[0] = 1.0f / sqrtf(sh[0]);
            g_scal[1] = 1.0f / sqrtf(sl[0]);
            float c = ch[0];
            g_scal[2] = (fminf(fmaxf(c + 3.0f, 0.0f), 6.0f) / 3.0f + 1e-6f) * 0.5f;
            c = cl[0];
            g_scal[3] = (fminf(fmaxf(c + 3.0f, 0.0f), 6.0f) / 3.0f + 1e-6f) * 0.5f;
        }
        if (t < F) {
            g_w[t]         = ah[t]     + ah[2*F+t] + ah[3*F+t];   // wh1
            g_w[F + t]     = ah[F+t]   + ah[2*F+t] - ah[3*F+t];   // wh2
            g_w[2*F + t]   = al[t];                                // vl1
            g_w[3*F + t]   = al[F+t];                              // vl2
            g_w[4*F + t]   = al[2*F+t] + al[3*F+t];                // vl3
            g_w[5*F + t]   = al[2*F+t] - al[3*F+t];                // vl4
        }
    }

    {
        int n = e >> 8;
        int k = e & 255;
        float v = (n < 64) ? Wh[(size_t)k * F + n] : Wl[(size_t)k * F + (n - 64)];
        __nv_bfloat16 hi, lo;
        split_bf16(v, hi, lo);
        g_Bt_h[e] = hi;
        g_Bt_l[e] = lo;
    }

    for (int i = e; i < NMAX + 4; i += 32768) g_deg[i] = 0;
}

// ---------------- CSR build ----------------
__global__ void count_kernel(const int* __restrict__ src, int E) {
    int i = blockIdx.x * blockDim.x + threadIdx.x;
    int stride = gridDim.x * blockDim.x;
    for (int e = i; e < E; e += stride) atomicAdd(&g_deg[__ldg(src + e)], 1);
}

__global__ void scan_kernel(int N) {
    __shared__ int part[1024];
    int t = threadIdx.x;
    int Cc = (((N + 1023) >> 10) + 3) & ~3;
    int base = t * Cc;
    int s = 0;
    for (int i = 0; i < Cc; i += 4) {
        int idx = base + i;
        if (idx < N) {
            int4 v = *(const int4*)&g_deg[idx];   // padded; beyond-N entries are 0
            s += v.x + v.y + v.z + v.w;
        }
    }
    part[t] = s;
    __syncthreads();
    for (int o = 1; o < 1024; o <<= 1) {
        int v = (t >= o) ? part[t - o] : 0;
        __syncthreads();
        part[t] += v;
        __syncthreads();
    }
    int run = part[t] - s;
    for (int i = 0; i < Cc; i += 4) {
        int idx = base + i;
        if (idx < N) {
            int4 v = *(const int4*)&g_deg[idx];
            int4 r;
            r.x = run;
            r.y = r.x + v.x;
            r.z = r.y + v.y;
            r.w = r.z + v.z;
            run = r.w + v.w;
            *(int4*)&g_rs[idx]  = r;
            *(int4*)&g_cur[idx] = r;
        }
    }
}

__global__ void fill_kernel(const int* __restrict__ src, const int* __restrict__ dst, int E) {
    int i = blockIdx.x * blockDim.x + threadIdx.x;
    int stride = gridDim.x * blockDim.x;
    for (int e = i; e < E; e += stride) {
        int s = __ldg(src + e);
        int pos = atomicAdd(&g_cur[s], 1);
        g_csr[pos] = __ldg(dst + e);
    }
}

// ---------------- K1: HMMA split-bf16 GEMM (256 thr, round-8 proven) + fused leaky + Q ----------------
#define ASTRIDE 40   // bf16 elements per smem row (32 + 8 pad)

__global__ void __launch_bounds__(256) gemm_tc_kernel(const float* __restrict__ X, int N) {
    __shared__ __nv_bfloat16 As_h[128 * ASTRIDE];
    __shared__ __nv_bfloat16 As_l[128 * ASTRIDE];
    __shared__ __nv_bfloat16 Bs_h[128 * ASTRIDE];
    __shared__ __nv_bfloat16 Bs_l[128 * ASTRIDE];
    __shared__ float sW[6 * F];        // folded weight vectors
    __shared__ float sQA[128][4];      // high-slab partial dots per row
    __shared__ float sQB[128][2];      // low-slab partial dots per row

    int tid  = threadIdx.x;
    int wid  = tid >> 5;
    int lane = tid & 31;
    int brow = blockIdx.x * 128;
    int warp_m = wid & 3;
    int warp_n = wid >> 2;

    if (tid < 128) {
        sW[tid]       = g_w[tid];
        sW[tid + 128] = g_w[tid + 128];
        sW[tid + 256] = g_w[tid + 256];
    }

    float acc[2][8][4];
    #pragma unroll
    for (int mi = 0; mi < 2; mi++)
        #pragma unroll
        for (int ni = 0; ni < 8; ni++)
            #pragma unroll
            for (int q = 0; q < 4; q++) acc[mi][ni][q] = 0.f;

    uint32_t sbAH = smem_u32(As_h), sbAL = smem_u32(As_l);
    uint32_t sbBH = smem_u32(Bs_h), sbBL = smem_u32(Bs_l);

    int a_r = lane & 15, a_c = (lane >> 4) << 3;
    int b_r = lane & 7;
    int b_n = ((lane >> 4) & 1) << 3;
    int b_k = ((lane >> 3) & 1) << 3;

    int arow[4], ac4[4];
    #pragma unroll
    for (int i = 0; i < 4; i++) {
        int idx = tid + 256 * i;
        arow[i] = idx >> 3;
        ac4[i]  = (idx & 7) << 2;
    }
    int bn[2], bk[2];
    #pragma unroll
    for (int i = 0; i < 2; i++) {
        int idx = tid + 256 * i;
        bn[i] = idx >> 2;
        bk[i] = (idx & 3) << 3;
    }

    float4 xa[4];
    uint4  pbh[2], pbl[2];

    #pragma unroll
    for (int i = 0; i < 4; i++) {
        int grow = brow + arow[i];
        xa[i] = (grow < N) ? *(const float4*)(X + (size_t)grow * DIN + ac4[i])
                           : make_float4(0.f, 0.f, 0.f, 0.f);
    }
    #pragma unroll
    for (int i = 0; i < 2; i++) {
        pbh[i] = *(const uint4*)(g_Bt_h + (size_t)bn[i] * 256 + bk[i]);
        pbl[i] = *(const uint4*)(g_Bt_l + (size_t)bn[i] * 256 + bk[i]);
    }

    for (int chunk = 0; chunk < 8; chunk++) {
        __syncthreads();
        #pragma unroll
        for (int i = 0; i < 4; i++) {
            float4 v = xa[i];
            __nv_bfloat16 h0, h1, h2, h3, l0, l1, l2, l3;
            split_bf16(v.x, h0, l0); split_bf16(v.y, h1, l1);
            split_bf16(v.z, h2, l2); split_bf16(v.w, h3, l3);
            int o = arow[i] * ASTRIDE + ac4[i];
            __nv_bfloat162 p;
            p.x = h0; p.y = h1; *(__nv_bfloat162*)&As_h[o]     = p;
            p.x = h2; p.y = h3; *(__nv_bfloat162*)&As_h[o + 2] = p;
            p.x = l0; p.y = l1; *(__nv_bfloat162*)&As_l[o]     = p;
            p.x = l2; p.y = l3; *(__nv_bfloat162*)&As_l[o + 2] = p;
        }
        #pragma unroll
        for (int i = 0; i < 2; i++) {
            *(uint4*)&Bs_h[bn[i] * ASTRIDE + bk[i]] = pbh[i];
            *(uint4*)&Bs_l[bn[i] * ASTRIDE + bk[i]] = pbl[i];
        }
        __syncthreads();

        if (chunk < 7) {
            int k0 = (chunk + 1) * 32;
            #pragma unroll
            for (int i = 0; i < 4; i++) {
                int grow = brow + arow[i];
                xa[i] = (grow < N) ? *(const float4*)(X + (size_t)grow * DIN + k0 + ac4[i])
                                   : make_float4(0.f, 0.f, 0.f, 0.f);
            }
            #pragma unroll
            for (int i = 0; i < 2; i++) {
                pbh[i] = *(const uint4*)(g_Bt_h + (size_t)bn[i] * 256 + k0 + bk[i]);
                pbl[i] = *(const uint4*)(g_Bt_l + (size_t)bn[i] * 256 + k0 + bk[i]);
            }
        }

        #pragma unroll
        for (int ks = 0; ks < 2; ks++) {
            int k16 = ks * 16;
            uint32_t ah[2][4], al[2][4];
            #pragma unroll
            for (int mi = 0; mi < 2; mi++) {
                uint32_t aoff = ((warp_m * 32 + mi * 16 + a_r) * ASTRIDE + k16 + a_c) * 2;
                LDMX4(ah[mi][0], ah[mi][1], ah[mi][2], ah[mi][3], sbAH + aoff);
                LDMX4(al[mi][0], al[mi][1], al[mi][2], al[mi][3], sbAL + aoff);
            }
            #pragma unroll
            for (int np = 0; np < 4; np++) {
                uint32_t boff = ((warp_n * 64 + np * 16 + b_n + b_r) * ASTRIDE + k16 + b_k) * 2;
                uint32_t bh[4], bl[4];
                LDMX4(bh[0], bh[1], bh[2], bh[3], sbBH + boff);
                LDMX4(bl[0], bl[1], bl[2], bl[3], sbBL + boff);
                #pragma unroll
                for (int mi = 0; mi < 2; mi++) {
                    #pragma unroll
                    for (int h = 0; h < 2; h++) {
                        float* d = acc[mi][np * 2 + h];
                        MMA16816(d, ah[mi], bh[2 * h], bh[2 * h + 1]);
                        MMA16816(d, ah[mi], bl[2 * h], bl[2 * h + 1]);
                        MMA16816(d, al[mi], bh[2 * h], bh[2 * h + 1]);
                    }
                }
            }
        }
    }

    // --- Epilogue: leaky + store H + fused per-row score dots ---
    __syncthreads();
    int rq   = lane >> 2;
    int col0 = warp_n * 64 + ((lane & 3) << 1);
    int cl0  = (lane & 3) << 1;
    float dots[2][2][4];
    #pragma unroll
    for (int mi = 0; mi < 2; mi++)
        #pragma unroll
        for (int rh = 0; rh < 2; rh++)
            #pragma unroll
            for (int q = 0; q < 4; q++) dots[mi][rh][q] = 0.f;

    #pragma unroll
    for (int mi = 0; mi < 2; mi++) {
        int r0 = brow + warp_m * 32 + mi * 16 + rq;
        #pragma unroll
        for (int ni = 0; ni < 8; ni++) {
            int c  = col0 + ni * 8;
            int lc = cl0 + ni * 8;
            float* d = acc[mi][ni];
            float h0 = leaky(d[0]), h1 = leaky(d[1]);
            float h2 = leaky(d[2]), h3 = leaky(d[3]);
            if (r0 < N)
                *(float2*)&g_ZH[(size_t)r0 * C2 + c] = make_float2(h0, h1);
            if (r0 + 8 < N)
                *(float2*)&g_ZH[(size_t)(r0 + 8) * C2 + c] = make_float2(h2, h3);
            if (warp_n == 0) {
                #pragma unroll
                for (int q = 0; q < 4; q++) {
                    float wa = sW[q * F + lc], wb = sW[q * F + lc + 1];
                    dots[mi][0][q] = fmaf(h0, wa, fmaf(h1, wb, dots[mi][0][q]));
                    dots[mi][1][q] = fmaf(h2, wa, fmaf(h3, wb, dots[mi][1][q]));
                }
            } else {
                #pragma unroll
                for (int q = 0; q < 2; q++) {
                    float wa = sW[(4 + q) * F + lc], wb = sW[(4 + q) * F + lc + 1];
                    dots[mi][0][q] = fmaf(h0, wa, fmaf(h1, wb, dots[mi][0][q]));
                    dots[mi][1][q] = fmaf(h2, wa, fmaf(h3, wb, dots[mi][1][q]));
                }
            }
        }
    }
    #pragma unroll
    for (int mi = 0; mi < 2; mi++)
        #pragma unroll
        for (int rh = 0; rh < 2; rh++)
            #pragma unroll
            for (int q = 0; q < 4; q++) {
                float v = dots[mi][rh][q];
                v += __shfl_xor_sync(0xffffffffu, v, 1);
                v += __shfl_xor_sync(0xffffffffu, v, 2);
                dots[mi][rh][q] = v;
            }
    if ((lane & 3) == 0) {
        #pragma unroll
        for (int mi = 0; mi < 2; mi++)
            #pragma unroll
            for (int rh = 0; rh < 2; rh++) {
                int row = warp_m * 32 + mi * 16 + rh * 8 + rq;
                if (warp_n == 0) {
                    sQA[row][0] = dots[mi][rh][0];
                    sQA[row][1] = dots[mi][rh][1];
                    sQA[row][2] = dots[mi][rh][2];
                    sQA[row][3] = dots[mi][rh][3];
                } else {
                    sQB[row][0] = dots[mi][rh][0];
                    sQB[row][1] = dots[mi][rh][1];
                }
            }
    }
    __syncthreads();
    if (tid < 128) {
        int grow = brow + tid;
        if (grow < N) {
            float inh = g_scal[0], inl = g_scal[1];
            g_Q[grow] = make_float4(sQA[tid][0] * inh,
                                    sQA[tid][1] * inh,
                                    (sQA[tid][2] + sQB[tid][0]) * inl,
                                    (sQA[tid][3] + sQB[tid][1]) * inl);
        }
    }
}

// ---------------- K3: CSR aggregation, warp per node, edge-parallel two-phase ----------------
__global__ void __launch_bounds__(256) agg_kernel(float* __restrict__ out, int N) {
    int gw   = (int)(((size_t)blockIdx.x * blockDim.x + threadIdx.x) >> 5);
    int lane = threadIdx.x & 31;
    if (gw >= N) return;
    float4 qs = g_Q[gw];
    int start = g_rs[gw];
    int end   = start + g_deg[gw];
    bool hi = lane < 16;
    float4 acc = make_float4(0.f, 0.f, 0.f, 0.f);
    float rsh = 0.f, rsl = 0.f;
    for (int base = start; base < end; base += 32) {
        int cnt = min(32, end - base);
        int   d_l  = 0;
        float eh_l = 0.f, el_l = 0.f;
        if (lane < cnt) {
            d_l = __ldg(&g_csr[base + lane]);
            float4 qd = __ldg(&g_Q[d_l]);
            float sch = qs.x + qd.y;
            float scl = qs.z + qd.w;
            eh_l = __expf(-fmaxf(sch, 0.2f * sch));
            el_l = __expf(-fmaxf(scl, 0.2f * scl));
        }
        rsh += eh_l;
        rsl += el_l;
        for (int j = 0; j < cnt; j++) {
            int   dj  = __shfl_sync(0xffffffffu, d_l, j);
            float ehj = __shfl_sync(0xffffffffu, eh_l, j);
            float elj = __shfl_sync(0xffffffffu, el_l, j);
            float4 hv = __ldg((const float4*)&g_ZH[(size_t)dj * C2 + lane * 4]);
            float ec = hi ? ehj : elj;
            acc.x = fmaf(hv.x, ec, acc.x);
            acc.y = fmaf(hv.y, ec, acc.y);
            acc.z = fmaf(hv.z, ec, acc.z);
            acc.w = fmaf(hv.w, ec, acc.w);
        }
    }
    #pragma unroll
    for (int o = 16; o; o >>= 1) {
        rsh += __shfl_xor_sync(0xffffffffu, rsh, o);
        rsl += __shfl_xor_sync(0xffffffffu, rsl, o);
    }
    float theta = hi ? g_scal[2] : g_scal[3];
    float inv = 1.0f / ((hi ? rsh : rsl) + theta);
    float4 v = make_float4(leaky(acc.x * inv), leaky(acc.y * inv),
                           leaky(acc.z * inv), leaky(acc.w * inv));
    *(float4*)(out + (size_t)gw * C2 + lane * 4) = v;
}

extern "C" void kernel_launch(void* const* d_in, const int* in_sizes, int n_in,
                              void* d_out, int out_size) {
    const float* X    = (const float*)d_in[0];
    const int*   edge = (const int*)d_in[1];
    const float* Wh   = (const float*)d_in[2];
    const float* Wl   = (const float*)d_in[3];
    const float* ah   = (const float*)d_in[4];
    const float* al   = (const float*)d_in[5];
    const float* ch   = (const float*)d_in[6];
    const float* cl   = (const float*)d_in[7];
    float* out = (float*)d_out;

    int N = in_sizes[0] / DIN;
    int E = in_sizes[1] / 2;

    // Side stream + events, created once on the first (non-captured) call.
    static cudaStream_t s2 = nullptr;
    static cudaEvent_t  evFork = nullptr, evJoin = nullptr;
    if (s2 == nullptr) {
        cudaStreamCreateWithFlags(&s2, cudaStreamNonBlocking);
        cudaEventCreateWithFlags(&evFork, cudaEventDisableTiming);
        cudaEventCreateWithFlags(&evJoin, cudaEventDisableTiming);
    }

    // setup (also zeroes g_deg) on the main stream
    setup_kernel<<<128, 256>>>(Wh, Wl, ah, al, ch, cl);

    // fork: CSR build on side stream, GEMM on main stream (independent dataflows)
    cudaEventRecord(evFork, 0);
    cudaStreamWaitEvent(s2, evFork, 0);

    count_kernel<<<2048, 256, 0, s2>>>(edge, E);
    scan_kernel<<<1, 1024, 0, s2>>>(N);
    fill_kernel<<<2048, 256, 0, s2>>>(edge, edge + E, E);
    cudaEventRecord(evJoin, s2);

    gemm_tc_kernel<<<(N + 127) / 128, 256>>>(X, N);

    // join: agg needs both CSR and H/Q
    cudaStreamWaitEvent(0, evJoin, 0);
    agg_kernel<<<(N * 32 + 255) / 256, 256>>>(out, N);
}

// round 12
// speedup vs baseline: 1.6413x; 1.0852x over previous
#include <cuda_runtime.h>
#include <cuda_bf16.h>
#include <cstdint>

#define NMAX 100000
#define EMAX 1600000
#define DIN  256
#define F    64
#define C2   128

// ---------------- scratch (device globals: allocation-free rule) ----------------
__device__ float  g_ZH[(size_t)NMAX * C2];   // H = leaky(X@W) rows
__device__ float4 g_Q[NMAX];                 // per-node score scalars, pre-scaled by 1/||a||
__device__ float  g_w[6 * F];                // folded a-vector combos
__device__ float  g_scal[4];                 // inv_norm_high, inv_norm_low, theta_high, theta_low
__device__ int    g_deg[NMAX + 4];
__device__ int    g_rs[NMAX + 4];            // CSR row start (exclusive prefix of deg)
__device__ int    g_cur[NMAX + 4];           // fill cursors
__device__ int    g_csr[EMAX];               // dst indices grouped by src
// Pre-split, pre-transposed B = [Wh|Wl]: [128 n][256 k] bf16 hi/lo images (L2-hot).
__device__ __align__(16) __nv_bfloat16 g_Bt_h[128 * 256];
__device__ __align__(16) __nv_bfloat16 g_Bt_l[128 * 256];

__device__ __forceinline__ float leaky(float x) { return fmaxf(x, 0.2f * x); }

__device__ __forceinline__ uint32_t smem_u32(const void* p) {
    uint32_t a;
    asm("{ .reg .u64 t; cvta.to.shared.u64 t, %1; cvt.u32.u64 %0, t; }" : "=r"(a) : "l"(p));
    return a;
}

__device__ __forceinline__ void split_bf16(float x, __nv_bfloat16& hi, __nv_bfloat16& lo) {
    hi = __float2bfloat16(x);
    lo = __float2bfloat16(x - __bfloat162float(hi));
}

#define LDMX4(r0, r1, r2, r3, addr) \
    asm volatile("ldmatrix.sync.aligned.m8n8.x4.shared.b16 {%0,%1,%2,%3}, [%4];" \
                 : "=r"(r0), "=r"(r1), "=r"(r2), "=r"(r3) : "r"(addr))

#define MMA16816(d, a, b0, b1) \
    asm volatile("mma.sync.aligned.m16n8k16.row.col.f32.bf16.bf16.f32 " \
                 "{%0,%1,%2,%3}, {%4,%5,%6,%7}, {%8,%9}, {%0,%1,%2,%3};" \
                 : "+f"((d)[0]), "+f"((d)[1]), "+f"((d)[2]), "+f"((d)[3]) \
                 : "r"((a)[0]), "r"((a)[1]), "r"((a)[2]), "r"((a)[3]), "r"(b0), "r"(b1))

// ---------------- K0: setup (prep scalars/weights + B images + zero deg) ----------------
__global__ void setup_kernel(const float* __restrict__ Wh, const float* __restrict__ Wl,
                             const float* __restrict__ ah, const float* __restrict__ al,
                             const float* __restrict__ ch, const float* __restrict__ cl) {
    int t = threadIdx.x;
    int e = blockIdx.x * 256 + t;        // 0..32767 over 128 blocks

    if (blockIdx.x == 0) {
        __shared__ float sh[256], sl[256];
        float vh = ah[t], vl = al[t];
        sh[t] = vh * vh; sl[t] = vl * vl;
        __syncthreads();
        for (int o = 128; o; o >>= 1) {
            if (t < o) { sh[t] += sh[t + o]; sl[t] += sl[t + o]; }
            __syncthreads();
        }
        if (t == 0) {
            g_scal[0] = 1.0f / sqrtf(sh[0]);
            g_scal[1] = 1.0f / sqrtf(sl[0]);
            float c = ch[0];
            g_scal[2] = (fminf(fmaxf(c + 3.0f, 0.0f), 6.0f) / 3.0f + 1e-6f) * 0.5f;
            c = cl[0];
            g_scal[3] = (fminf(fmaxf(c + 3.0f, 0.0f), 6.0f) / 3.0f + 1e-6f) * 0.5f;
        }
        if (t < F) {
            g_w[t]         = ah[t]     + ah[2*F+t] + ah[3*F+t];   // wh1
            g_w[F + t]     = ah[F+t]   + ah[2*F+t] - ah[3*F+t];   // wh2
            g_w[2*F + t]   = al[t];                                // vl1
            g_w[3*F + t]   = al[F+t];                              // vl2
            g_w[4*F + t]   = al[2*F+t] + al[3*F+t];                // vl3
            g_w[5*F + t]   = al[2*F+t] - al[3*F+t];                // vl4
        }
    }

    {
        int n = e >> 8;
        int k = e & 255;
        float v = (n < 64) ? Wh[(size_t)k * F + n] : Wl[(size_t)k * F + (n - 64)];
        __nv_bfloat16 hi, lo;
        split_bf16(v, hi, lo);
        g_Bt_h[e] = hi;
        g_Bt_l[e] = lo;
    }

    for (int i = e; i < NMAX + 4; i += 32768) g_deg[i] = 0;
}

// ---------------- CSR build ----------------
__global__ void count_kernel(const int* __restrict__ src, int E) {
    int i = blockIdx.x * blockDim.x + threadIdx.x;
    int stride = gridDim.x * blockDim.x;
    for (int e = i; e < E; e += stride) atomicAdd(&g_deg[__ldg(src + e)], 1);
}

__global__ void scan_kernel(int N) {
    __shared__ int part[1024];
    int t = threadIdx.x;
    int Cc = (((N + 1023) >> 10) + 3) & ~3;
    int base = t * Cc;
    int s = 0;
    for (int i = 0; i < Cc; i += 4) {
        int idx = base + i;
        if (idx < N) {
            int4 v = *(const int4*)&g_deg[idx];   // padded; beyond-N entries are 0
            s += v.x + v.y + v.z + v.w;
        }
    }
    part[t] = s;
    __syncthreads();
    for (int o = 1; o < 1024; o <<= 1) {
        int v = (t >= o) ? part[t - o] : 0;
        __syncthreads();
        part[t] += v;
        __syncthreads();
    }
    int run = part[t] - s;
    for (int i = 0; i < Cc; i += 4) {
        int idx = base + i;
        if (idx < N) {
            int4 v = *(const int4*)&g_deg[idx];
            int4 r;
            r.x = run;
            r.y = r.x + v.x;
            r.z = r.y + v.y;
            r.w = r.z + v.z;
            run = r.w + v.w;
            *(int4*)&g_rs[idx]  = r;
            *(int4*)&g_cur[idx] = r;
        }
    }
}

__global__ void fill_kernel(const int* __restrict__ src, const int* __restrict__ dst, int E) {
    int i = blockIdx.x * blockDim.x + threadIdx.x;
    int stride = gridDim.x * blockDim.x;
    for (int e = i; e < E; e += stride) {
        int s = __ldg(src + e);
        int pos = atomicAdd(&g_cur[s], 1);
        g_csr[pos] = __ldg(dst + e);
    }
}

// ---------------- K1: HMMA split-bf16 GEMM, 2 CTAs/SM, direct loads + fused leaky + Q ----------------
#define ASTRIDE 40   // bf16 elements per smem row (32 + 8 pad)

__global__ void __launch_bounds__(256, 2) gemm_tc_kernel(const float* __restrict__ X, int N) {
    __shared__ __nv_bfloat16 As_h[128 * ASTRIDE];
    __shared__ __nv_bfloat16 As_l[128 * ASTRIDE];
    __shared__ __nv_bfloat16 Bs_h[128 * ASTRIDE];
    __shared__ __nv_bfloat16 Bs_l[128 * ASTRIDE];
    __shared__ float sW[6 * F];        // folded weight vectors
    __shared__ float sQA[128][4];      // high-slab partial dots per row
    __shared__ float sQB[128][2];      // low-slab partial dots per row

    int tid  = threadIdx.x;
    int wid  = tid >> 5;
    int lane = tid & 31;
    int brow = blockIdx.x * 128;
    int warp_m = wid & 3;
    int warp_n = wid >> 2;

    if (tid < 128) {
        sW[tid]       = g_w[tid];
        sW[tid + 128] = g_w[tid + 128];
        sW[tid + 256] = g_w[tid + 256];
    }

    float acc[2][8][4];
    #pragma unroll
    for (int mi = 0; mi < 2; mi++)
        #pragma unroll
        for (int ni = 0; ni < 8; ni++)
            #pragma unroll
            for (int q = 0; q < 4; q++) acc[mi][ni][q] = 0.f;

    uint32_t sbAH = smem_u32(As_h), sbAL = smem_u32(As_l);
    uint32_t sbBH = smem_u32(Bs_h), sbBL = smem_u32(Bs_l);

    int a_r = lane & 15, a_c = (lane >> 4) << 3;
    int b_r = lane & 7;
    int b_n = ((lane >> 4) & 1) << 3;
    int b_k = ((lane >> 3) & 1) << 3;

    int arow[4], ac4[4];
    #pragma unroll
    for (int i = 0; i < 4; i++) {
        int idx = tid + 256 * i;
        arow[i] = idx >> 3;
        ac4[i]  = (idx & 7) << 2;
    }
    int bn[2], bk[2];
    #pragma unroll
    for (int i = 0; i < 2; i++) {
        int idx = tid + 256 * i;
        bn[i] = idx >> 2;
        bk[i] = (idx & 3) << 3;
    }

    for (int chunk = 0; chunk < 8; chunk++) {
        int k0 = chunk * 32;
        __syncthreads();   // smem free (prev MMA done)
        // A: load X fp32, split hi/lo -> smem (direct; latency hidden by 2-CTA overlap)
        #pragma unroll
        for (int i = 0; i < 4; i++) {
            int grow = brow + arow[i];
            float4 v = (grow < N) ? *(const float4*)(X + (size_t)grow * DIN + k0 + ac4[i])
                                  : make_float4(0.f, 0.f, 0.f, 0.f);
            __nv_bfloat16 h0, h1, h2, h3, l0, l1, l2, l3;
            split_bf16(v.x, h0, l0); split_bf16(v.y, h1, l1);
            split_bf16(v.z, h2, l2); split_bf16(v.w, h3, l3);
            int o = arow[i] * ASTRIDE + ac4[i];
            __nv_bfloat162 p;
            p.x = h0; p.y = h1; *(__nv_bfloat162*)&As_h[o]     = p;
            p.x = h2; p.y = h3; *(__nv_bfloat162*)&As_h[o + 2] = p;
            p.x = l0; p.y = l1; *(__nv_bfloat162*)&As_l[o]     = p;
            p.x = l2; p.y = l3; *(__nv_bfloat162*)&As_l[o + 2] = p;
        }
        // B: copy pre-split images (L2-hot)
        #pragma unroll
        for (int i = 0; i < 2; i++) {
            uint4 vh = *(const uint4*)(g_Bt_h + (size_t)bn[i] * 256 + k0 + bk[i]);
            uint4 vl = *(const uint4*)(g_Bt_l + (size_t)bn[i] * 256 + k0 + bk[i]);
            *(uint4*)&Bs_h[bn[i] * ASTRIDE + bk[i]] = vh;
            *(uint4*)&Bs_l[bn[i] * ASTRIDE + bk[i]] = vl;
        }
        __syncthreads();   // smem ready

        #pragma unroll
        for (int ks = 0; ks < 2; ks++) {
            int k16 = ks * 16;
            uint32_t ah[2][4], al[2][4];
            #pragma unroll
            for (int mi = 0; mi < 2; mi++) {
                uint32_t aoff = ((warp_m * 32 + mi * 16 + a_r) * ASTRIDE + k16 + a_c) * 2;
                LDMX4(ah[mi][0], ah[mi][1], ah[mi][2], ah[mi][3], sbAH + aoff);
                LDMX4(al[mi][0], al[mi][1], al[mi][2], al[mi][3], sbAL + aoff);
            }
            #pragma unroll
            for (int np = 0; np < 4; np++) {
                uint32_t boff = ((warp_n * 64 + np * 16 + b_n + b_r) * ASTRIDE + k16 + b_k) * 2;
                uint32_t bh[4], bl[4];
                LDMX4(bh[0], bh[1], bh[2], bh[3], sbBH + boff);
                LDMX4(bl[0], bl[1], bl[2], bl[3], sbBL + boff);
                #pragma unroll
                for (int mi = 0; mi < 2; mi++) {
                    #pragma unroll
                    for (int h = 0; h < 2; h++) {
                        float* d = acc[mi][np * 2 + h];
                        MMA16816(d, ah[mi], bh[2 * h], bh[2 * h + 1]);
                        MMA16816(d, ah[mi], bl[2 * h], bl[2 * h + 1]);
                        MMA16816(d, al[mi], bh[2 * h], bh[2 * h + 1]);
                    }
                }
            }
        }
    }

    // --- Epilogue: leaky + store H + fused per-row score dots ---
    __syncthreads();
    int rq   = lane >> 2;
    int col0 = warp_n * 64 + ((lane & 3) << 1);
    int cl0  = (lane & 3) << 1;
    float dots[2][2][4];
    #pragma unroll
    for (int mi = 0; mi < 2; mi++)
        #pragma unroll
        for (int rh = 0; rh < 2; rh++)
            #pragma unroll
            for (int q = 0; q < 4; q++) dots[mi][rh][q] = 0.f;

    #pragma unroll
    for (int mi = 0; mi < 2; mi++) {
        int r0 = brow + warp_m * 32 + mi * 16 + rq;
        #pragma unroll
        for (int ni = 0; ni < 8; ni++) {
            int c  = col0 + ni * 8;
            int lc = cl0 + ni * 8;
            float* d = acc[mi][ni];
            float h0 = leaky(d[0]), h1 = leaky(d[1]);
            float h2 = leaky(d[2]), h3 = leaky(d[3]);
            if (r0 < N)
                *(float2*)&g_ZH[(size_t)r0 * C2 + c] = make_float2(h0, h1);
            if (r0 + 8 < N)
                *(float2*)&g_ZH[(size_t)(r0 + 8) * C2 + c] = make_float2(h2, h3);
            if (warp_n == 0) {
                #pragma unroll
                for (int q = 0; q < 4; q++) {
                    float wa = sW[q * F + lc], wb = sW[q * F + lc + 1];
                    dots[mi][0][q] = fmaf(h0, wa, fmaf(h1, wb, dots[mi][0][q]));
                    dots[mi][1][q] = fmaf(h2, wa, fmaf(h3, wb, dots[mi][1][q]));
                }
            } else {
                #pragma unroll
                for (int q = 0; q < 2; q++) {
                    float wa = sW[(4 + q) * F + lc], wb = sW[(4 + q) * F + lc + 1];
                    dots[mi][0][q] = fmaf(h0, wa, fmaf(h1, wb, dots[mi][0][q]));
                    dots[mi][1][q] = fmaf(h2, wa, fmaf(h3, wb, dots[mi][1][q]));
                }
            }
        }
    }
    #pragma unroll
    for (int mi = 0; mi < 2; mi++)
        #pragma unroll
        for (int rh = 0; rh < 2; rh++)
            #pragma unroll
            for (int q = 0; q < 4; q++) {
                float v = dots[mi][rh][q];
                v += __shfl_xor_sync(0xffffffffu, v, 1);
                v += __shfl_xor_sync(0xffffffffu, v, 2);
                dots[mi][rh][q] = v;
            }
    if ((lane & 3) == 0) {
        #pragma unroll
        for (int mi = 0; mi < 2; mi++)
            #pragma unroll
            for (int rh = 0; rh < 2; rh++) {
                int row = warp_m * 32 + mi * 16 + rh * 8 + rq;
                if (warp_n == 0) {
                    sQA[row][0] = dots[mi][rh][0];
                    sQA[row][1] = dots[mi][rh][1];
                    sQA[row][2] = dots[mi][rh][2];
                    sQA[row][3] = dots[mi][rh][3];
                } else {
                    sQB[row][0] = dots[mi][rh][0];
                    sQB[row][1] = dots[mi][rh][1];
                }
            }
    }
    __syncthreads();
    if (tid < 128) {
        int grow = brow + tid;
        if (grow < N) {
            float inh = g_scal[0], inl = g_scal[1];
            g_Q[grow] = make_float4(sQA[tid][0] * inh,
                                    sQA[tid][1] * inh,
                                    (sQA[tid][2] + sQB[tid][0]) * inl,
                                    (sQA[tid][3] + sQB[tid][1]) * inl);
        }
    }
}

// ---------------- K3: CSR aggregation, warp per node, edge-parallel two-phase ----------------
__global__ void __launch_bounds__(256) agg_kernel(float* __restrict__ out, int N) {
    int gw   = (int)(((size_t)blockIdx.x * blockDim.x + threadIdx.x) >> 5);
    int lane = threadIdx.x & 31;
    if (gw >= N) return;
    float4 qs = g_Q[gw];
    int start = g_rs[gw];
    int end   = start + g_deg[gw];
    bool hi = lane < 16;
    float4 acc = make_float4(0.f, 0.f, 0.f, 0.f);
    float rsh = 0.f, rsl = 0.f;
    for (int base = start; base < end; base += 32) {
        int cnt = min(32, end - base);
        int   d_l  = 0;
        float eh_l = 0.f, el_l = 0.f;
        if (lane < cnt) {
            d_l = __ldg(&g_csr[base + lane]);
            float4 qd = __ldg(&g_Q[d_l]);
            float sch = qs.x + qd.y;
            float scl = qs.z + qd.w;
            eh_l = __expf(-fmaxf(sch, 0.2f * sch));
            el_l = __expf(-fmaxf(scl, 0.2f * scl));
        }
        rsh += eh_l;
        rsl += el_l;
        for (int j = 0; j < cnt; j++) {
            int   dj  = __shfl_sync(0xffffffffu, d_l, j);
            float ehj = __shfl_sync(0xffffffffu, eh_l, j);
            float elj = __shfl_sync(0xffffffffu, el_l, j);
            float4 hv = __ldg((const float4*)&g_ZH[(size_t)dj * C2 + lane * 4]);
            float ec = hi ? ehj : elj;
            acc.x = fmaf(hv.x, ec, acc.x);
            acc.y = fmaf(hv.y, ec, acc.y);
            acc.z = fmaf(hv.z, ec, acc.z);
            acc.w = fmaf(hv.w, ec, acc.w);
        }
    }
    #pragma unroll
    for (int o = 16; o; o >>= 1) {
        rsh += __shfl_xor_sync(0xffffffffu, rsh, o);
        rsl += __shfl_xor_sync(0xffffffffu, rsl, o);
    }
    float theta = hi ? g_scal[2] : g_scal[3];
    float inv = 1.0f / ((hi ? rsh : rsl) + theta);
    float4 v = make_float4(leaky(acc.x * inv), leaky(acc.y * inv),
                           leaky(acc.z * inv), leaky(acc.w * inv));
    *(float4*)(out + (size_t)gw * C2 + lane * 4) = v;
}

extern "C" void kernel_launch(void* const* d_in, const int* in_sizes, int n_in,
                              void* d_out, int out_size) {
    const float* X    = (const float*)d_in[0];
    const int*   edge = (const int*)d_in[1];
    const float* Wh   = (const float*)d_in[2];
    const float* Wl   = (const float*)d_in[3];
    const float* ah   = (const float*)d_in[4];
    const float* al   = (const float*)d_in[5];
    const float* ch   = (const float*)d_in[6];
    const float* cl   = (const float*)d_in[7];
    float* out = (float*)d_out;

    int N = in_sizes[0] / DIN;
    int E = in_sizes[1] / 2;

    // Side stream + events, created once on the first (non-captured) call.
    static cudaStream_t s2 = nullptr;
    static cudaEvent_t  evFork = nullptr, evJoin = nullptr;
    if (s2 == nullptr) {
        cudaStreamCreateWithFlags(&s2, cudaStreamNonBlocking);
        cudaEventCreateWithFlags(&evFork, cudaEventDisableTiming);
        cudaEventCreateWithFlags(&evJoin, cudaEventDisableTiming);
    }

    // setup (also zeroes g_deg) on the main stream
    setup_kernel<<<128, 256>>>(Wh, Wl, ah, al, ch, cl);

    // fork: CSR build on side stream, GEMM on main stream (independent dataflows)
    cudaEventRecord(evFork, 0);
    cudaStreamWaitEvent(s2, evFork, 0);

    count_kernel<<<2048, 256, 0, s2>>>(edge, E);
    scan_kernel<<<1, 1024, 0, s2>>>(N);
    fill_kernel<<<2048, 256, 0, s2>>>(edge, edge + E, E);
    cudaEventRecord(evJoin, s2);

    gemm_tc_kernel<<<(N + 127) / 128, 256>>>(X, N);

    // join: agg needs both CSR and H/Q
    cudaStreamWaitEvent(0, evJoin, 0);
    agg_kernel<<<(N * 32 + 255) / 256, 256>>>(out, N);
}

// round 14
// speedup vs baseline: 1.7726x; 1.0800x over previous
#include <cuda_runtime.h>
#include <cuda_bf16.h>
#include <cuda_fp16.h>
#include <cstdint>

#define NMAX 100000
#define EMAX 1600000
#define DIN  256
#define F    64
#define C2   128

// ---------------- scratch (device globals: allocation-free rule) ----------------
__device__ __align__(16) __half g_ZH[(size_t)NMAX * C2];   // H = leaky(X@W), fp16 rows
__device__ float4 g_Q[NMAX];                 // per-node score scalars, pre-scaled by 1/||a||
__device__ float  g_w[6 * F];                // folded a-vector combos
__device__ float  g_scal[4];                 // inv_norm_high, inv_norm_low, theta_high, theta_low
__device__ int    g_deg[NMAX + 4];
__device__ int    g_rs[NMAX + 4];            // CSR row start (exclusive prefix of deg)
__device__ int    g_cur[NMAX + 4];           // fill cursors
__device__ int    g_csr[EMAX];               // dst indices grouped by src
// Pre-split, pre-transposed B = [Wh|Wl]: [128 n][256 k] bf16 hi/lo images (L2-hot).
__device__ __align__(16) __nv_bfloat16 g_Bt_h[128 * 256];
__device__ __align__(16) __nv_bfloat16 g_Bt_l[128 * 256];

__device__ __forceinline__ float leaky(float x) { return fmaxf(x, 0.2f * x); }

__device__ __forceinline__ uint32_t smem_u32(const void* p) {
    uint32_t a;
    asm("{ .reg .u64 t; cvta.to.shared.u64 t, %1; cvt.u32.u64 %0, t; }" : "=r"(a) : "l"(p));
    return a;
}

__device__ __forceinline__ void split_bf16(float x, __nv_bfloat16& hi, __nv_bfloat16& lo) {
    hi = __float2bfloat16(x);
    lo = __float2bfloat16(x - __bfloat162float(hi));
}

#define LDMX4(r0, r1, r2, r3, addr) \
    asm volatile("ldmatrix.sync.aligned.m8n8.x4.shared.b16 {%0,%1,%2,%3}, [%4];" \
                 : "=r"(r0), "=r"(r1), "=r"(r2), "=r"(r3) : "r"(addr))

#define MMA16816(d, a, b0, b1) \
    asm volatile("mma.sync.aligned.m16n8k16.row.col.f32.bf16.bf16.f32 " \
                 "{%0,%1,%2,%3}, {%4,%5,%6,%7}, {%8,%9}, {%0,%1,%2,%3};" \
                 : "+f"((d)[0]), "+f"((d)[1]), "+f"((d)[2]), "+f"((d)[3]) \
                 : "r"((a)[0]), "r"((a)[1]), "r"((a)[2]), "r"((a)[3]), "r"(b0), "r"(b1))

// ---------------- K0: setup (prep scalars/weights + B images + zero deg) ----------------
__global__ void setup_kernel(const float* __restrict__ Wh, const float* __restrict__ Wl,
                             const float* __restrict__ ah, const float* __restrict__ al,
                             const float* __restrict__ ch, const float* __restrict__ cl) {
    int t = threadIdx.x;
    int e = blockIdx.x * 256 + t;        // 0..32767 over 128 blocks

    if (blockIdx.x == 0) {
        __shared__ float sh[256], sl[256];
        float vh = ah[t], vl = al[t];
        sh[t] = vh * vh; sl[t] = vl * vl;
        __syncthreads();
        for (int o = 128; o; o >>= 1) {
            if (t < o) { sh[t] += sh[t + o]; sl[t] += sl[t + o]; }
            __syncthreads();
        }
        if (t == 0) {
            g_scal[0] = 1.0f / sqrtf(sh[0]);
            g_scal[1] = 1.0f / sqrtf(sl[0]);
            float c = ch[0];
            g_scal[2] = (fminf(fmaxf(c + 3.0f, 0.0f), 6.0f) / 3.0f + 1e-6f) * 0.5f;
            c = cl[0];
            g_scal[3] = (fminf(fmaxf(c + 3.0f, 0.0f), 6.0f) / 3.0f + 1e-6f) * 0.5f;
        }
        if (t < F) {
            g_w[t]         = ah[t]     + ah[2*F+t] + ah[3*F+t];   // wh1
            g_w[F + t]     = ah[F+t]   + ah[2*F+t] - ah[3*F+t];   // wh2
            g_w[2*F + t]   = al[t];                                // vl1
            g_w[3*F + t]   = al[F+t];                              // vl2
            g_w[4*F + t]   = al[2*F+t] + al[3*F+t];                // vl3
            g_w[5*F + t]   = al[2*F+t] - al[3*F+t];                // vl4
        }
    }

    {
        int n = e >> 8;
        int k = e & 255;
        float v = (n < 64) ? Wh[(size_t)k * F + n] : Wl[(size_t)k * F + (n - 64)];
        __nv_bfloat16 hi, lo;
        split_bf16(v, hi, lo);
        g_Bt_h[e] = hi;
        g_Bt_l[e] = lo;
    }

    for (int i = e; i < NMAX + 4; i += 32768) g_deg[i] = 0;
}

// ---------------- CSR build ----------------
__global__ void count_kernel(const int* __restrict__ src, int E) {
    int i = blockIdx.x * blockDim.x + threadIdx.x;
    int stride = gridDim.x * blockDim.x;
    for (int e = i; e < E; e += stride) atomicAdd(&g_deg[__ldg(src + e)], 1);
}

__global__ void scan_kernel(int N) {
    __shared__ int part[1024];
    int t = threadIdx.x;
    int Cc = (((N + 1023) >> 10) + 3) & ~3;
    int base = t * Cc;
    int s = 0;
    for (int i = 0; i < Cc; i += 4) {
        int idx = base + i;
        if (idx < N) {
            int4 v = *(const int4*)&g_deg[idx];   // padded; beyond-N entries are 0
            s += v.x + v.y + v.z + v.w;
        }
    }
    part[t] = s;
    __syncthreads();
    for (int o = 1; o < 1024; o <<= 1) {
        int v = (t >= o) ? part[t - o] : 0;
        __syncthreads();
        part[t] += v;
        __syncthreads();
    }
    int run = part[t] - s;
    for (int i = 0; i < Cc; i += 4) {
        int idx = base + i;
        if (idx < N) {
            int4 v = *(const int4*)&g_deg[idx];
            int4 r;
            r.x = run;
            r.y = r.x + v.x;
            r.z = r.y + v.y;
            r.w = r.z + v.z;
            run = r.w + v.w;
            *(int4*)&g_rs[idx]  = r;
            *(int4*)&g_cur[idx] = r;
        }
    }
}

__global__ void fill_kernel(const int* __restrict__ src, const int* __restrict__ dst, int E) {
    int i = blockIdx.x * blockDim.x + threadIdx.x;
    int stride = gridDim.x * blockDim.x;
    for (int e = i; e < E; e += stride) {
        int s = __ldg(src + e);
        int pos = atomicAdd(&g_cur[s], 1);
        g_csr[pos] = __ldg(dst + e);
    }
}

// ---------------- K1: HMMA split-bf16 GEMM, 2 CTAs/SM + fused leaky + Q, fp16 H out ----------------
#define ASTRIDE 40   // bf16 elements per smem row (32 + 8 pad)

__global__ void __launch_bounds__(256, 2) gemm_tc_kernel(const float* __restrict__ X, int N) {
    __shared__ __nv_bfloat16 As_h[128 * ASTRIDE];
    __shared__ __nv_bfloat16 As_l[128 * ASTRIDE];
    __shared__ __nv_bfloat16 Bs_h[128 * ASTRIDE];
    __shared__ __nv_bfloat16 Bs_l[128 * ASTRIDE];
    __shared__ float sW[6 * F];        // folded weight vectors
    __shared__ float sQA[128][4];      // high-slab partial dots per row
    __shared__ float sQB[128][2];      // low-slab partial dots per row

    int tid  = threadIdx.x;
    int wid  = tid >> 5;
    int lane = tid & 31;
    int brow = blockIdx.x * 128;
    int warp_m = wid & 3;
    int warp_n = wid >> 2;

    if (tid < 128) {
        sW[tid]       = g_w[tid];
        sW[tid + 128] = g_w[tid + 128];
        sW[tid + 256] = g_w[tid + 256];
    }

    float acc[2][8][4];
    #pragma unroll
    for (int mi = 0; mi < 2; mi++)
        #pragma unroll
        for (int ni = 0; ni < 8; ni++)
            #pragma unroll
            for (int q = 0; q < 4; q++) acc[mi][ni][q] = 0.f;

    uint32_t sbAH = smem_u32(As_h), sbAL = smem_u32(As_l);
    uint32_t sbBH = smem_u32(Bs_h), sbBL = smem_u32(Bs_l);

    int a_r = lane & 15, a_c = (lane >> 4) << 3;
    int b_r = lane & 7;
    int b_n = ((lane >> 4) & 1) << 3;
    int b_k = ((lane >> 3) & 1) << 3;

    int arow[4], ac4[4];
    #pragma unroll
    for (int i = 0; i < 4; i++) {
        int idx = tid + 256 * i;
        arow[i] = idx >> 3;
        ac4[i]  = (idx & 7) << 2;
    }
    int bn[2], bk[2];
    #pragma unroll
    for (int i = 0; i < 2; i++) {
        int idx = tid + 256 * i;
        bn[i] = idx >> 2;
        bk[i] = (idx & 3) << 3;
    }

    for (int chunk = 0; chunk < 8; chunk++) {
        int k0 = chunk * 32;
        __syncthreads();   // smem free (prev MMA done)
        // A: load X fp32, split hi/lo -> smem (latency hidden by 2-CTA overlap)
        #pragma unroll
        for (int i = 0; i < 4; i++) {
            int grow = brow + arow[i];
            float4 v = (grow < N) ? *(const float4*)(X + (size_t)grow * DIN + k0 + ac4[i])
                                  : make_float4(0.f, 0.f, 0.f, 0.f);
            __nv_bfloat16 h0, h1, h2, h3, l0, l1, l2, l3;
            split_bf16(v.x, h0, l0); split_bf16(v.y, h1, l1);
            split_bf16(v.z, h2, l2); split_bf16(v.w, h3, l3);
            int o = arow[i] * ASTRIDE + ac4[i];
            __nv_bfloat162 p;
            p.x = h0; p.y = h1; *(__nv_bfloat162*)&As_h[o]     = p;
            p.x = h2; p.y = h3; *(__nv_bfloat162*)&As_h[o + 2] = p;
            p.x = l0; p.y = l1; *(__nv_bfloat162*)&As_l[o]     = p;
            p.x = l2; p.y = l3; *(__nv_bfloat162*)&As_l[o + 2] = p;
        }
        // B: copy pre-split images (L2-hot)
        #pragma unroll
        for (int i = 0; i < 2; i++) {
            uint4 vh = *(const uint4*)(g_Bt_h + (size_t)bn[i] * 256 + k0 + bk[i]);
            uint4 vl = *(const uint4*)(g_Bt_l + (size_t)bn[i] * 256 + k0 + bk[i]);
            *(uint4*)&Bs_h[bn[i] * ASTRIDE + bk[i]] = vh;
            *(uint4*)&Bs_l[bn[i] * ASTRIDE + bk[i]] = vl;
        }
        __syncthreads();   // smem ready

        #pragma unroll
        for (int ks = 0; ks < 2; ks++) {
            int k16 = ks * 16;
            uint32_t ah[2][4], al[2][4];
            #pragma unroll
            for (int mi = 0; mi < 2; mi++) {
                uint32_t aoff = ((warp_m * 32 + mi * 16 + a_r) * ASTRIDE + k16 + a_c) * 2;
                LDMX4(ah[mi][0], ah[mi][1], ah[mi][2], ah[mi][3], sbAH + aoff);
                LDMX4(al[mi][0], al[mi][1], al[mi][2], al[mi][3], sbAL + aoff);
            }
            #pragma unroll
            for (int np = 0; np < 4; np++) {
                uint32_t boff = ((warp_n * 64 + np * 16 + b_n + b_r) * ASTRIDE + k16 + b_k) * 2;
                uint32_t bh[4], bl[4];
                LDMX4(bh[0], bh[1], bh[2], bh[3], sbBH + boff);
                LDMX4(bl[0], bl[1], bl[2], bl[3], sbBL + boff);
                #pragma unroll
                for (int mi = 0; mi < 2; mi++) {
                    #pragma unroll
                    for (int h = 0; h < 2; h++) {
                        float* d = acc[mi][np * 2 + h];
                        MMA16816(d, ah[mi], bh[2 * h], bh[2 * h + 1]);
                        MMA16816(d, ah[mi], bl[2 * h], bl[2 * h + 1]);
                        MMA16816(d, al[mi], bh[2 * h], bh[2 * h + 1]);
                    }
                }
            }
        }
    }

    // --- Epilogue: leaky + store H (fp16) + fused per-row score dots ---
    __syncthreads();
    int rq   = lane >> 2;
    int col0 = warp_n * 64 + ((lane & 3) << 1);
    int cl0  = (lane & 3) << 1;
    float dots[2][2][4];
    #pragma unroll
    for (int mi = 0; mi < 2; mi++)
        #pragma unroll
        for (int rh = 0; rh < 2; rh++)
            #pragma unroll
            for (int q = 0; q < 4; q++) dots[mi][rh][q] = 0.f;

    #pragma unroll
    for (int mi = 0; mi < 2; mi++) {
        int r0 = brow + warp_m * 32 + mi * 16 + rq;
        #pragma unroll
        for (int ni = 0; ni < 8; ni++) {
            int c  = col0 + ni * 8;
            int lc = cl0 + ni * 8;
            float* d = acc[mi][ni];
            float h0 = leaky(d[0]), h1 = leaky(d[1]);
            float h2 = leaky(d[2]), h3 = leaky(d[3]);
            if (r0 < N)
                *(__half2*)&g_ZH[(size_t)r0 * C2 + c] = __floats2half2_rn(h0, h1);
            if (r0 + 8 < N)
                *(__half2*)&g_ZH[(size_t)(r0 + 8) * C2 + c] = __floats2half2_rn(h2, h3);
            if (warp_n == 0) {
                #pragma unroll
                for (int q = 0; q < 4; q++) {
                    float wa = sW[q * F + lc], wb = sW[q * F + lc + 1];
                    dots[mi][0][q] = fmaf(h0, wa, fmaf(h1, wb, dots[mi][0][q]));
                    dots[mi][1][q] = fmaf(h2, wa, fmaf(h3, wb, dots[mi][1][q]));
                }
            } else {
                #pragma unroll
                for (int q = 0; q < 2; q++) {
                    float wa = sW[(4 + q) * F + lc], wb = sW[(4 + q) * F + lc + 1];
                    dots[mi][0][q] = fmaf(h0, wa, fmaf(h1, wb, dots[mi][0][q]));
                    dots[mi][1][q] = fmaf(h2, wa, fmaf(h3, wb, dots[mi][1][q]));
                }
            }
        }
    }
    #pragma unroll
    for (int mi = 0; mi < 2; mi++)
        #pragma unroll
        for (int rh = 0; rh < 2; rh++)
            #pragma unroll
            for (int q = 0; q < 4; q++) {
                float v = dots[mi][rh][q];
                v += __shfl_xor_sync(0xffffffffu, v, 1);
                v += __shfl_xor_sync(0xffffffffu, v, 2);
                dots[mi][rh][q] = v;
            }
    if ((lane & 3) == 0) {
        #pragma unroll
        for (int mi = 0; mi < 2; mi++)
            #pragma unroll
            for (int rh = 0; rh < 2; rh++) {
                int row = warp_m * 32 + mi * 16 + rh * 8 + rq;
                if (warp_n == 0) {
                    sQA[row][0] = dots[mi][rh][0];
                    sQA[row][1] = dots[mi][rh][1];
                    sQA[row][2] = dots[mi][rh][2];
                    sQA[row][3] = dots[mi][rh][3];
                } else {
                    sQB[row][0] = dots[mi][rh][0];
                    sQB[row][1] = dots[mi][rh][1];
                }
            }
    }
    __syncthreads();
    if (tid < 128) {
        int grow = brow + tid;
        if (grow < N) {
            float inh = g_scal[0], inl = g_scal[1];
            g_Q[grow] = make_float4(sQA[tid][0] * inh,
                                    sQA[tid][1] * inh,
                                    (sQA[tid][2] + sQB[tid][0]) * inl,
                                    (sQA[tid][3] + sQB[tid][1]) * inl);
        }
    }
}

// ---------------- K3: CSR aggregation, warp per node, edge-parallel two-phase, fp16 H ----------------
__global__ void __launch_bounds__(256) agg_kernel(float* __restrict__ out, int N) {
    int gw   = (int)(((size_t)blockIdx.x * blockDim.x + threadIdx.x) >> 5);
    int lane = threadIdx.x & 31;
    if (gw >= N) return;
    float4 qs = g_Q[gw];
    int start = g_rs[gw];
    int end   = start + g_deg[gw];
    bool hi = lane < 16;
    float4 acc = make_float4(0.f, 0.f, 0.f, 0.f);
    float rsh = 0.f, rsl = 0.f;
    for (int base = start; base < end; base += 32) {
        int cnt = min(32, end - base);
        int   d_l  = 0;
        float eh_l = 0.f, el_l = 0.f;
        if (lane < cnt) {
            d_l = __ldg(&g_csr[base + lane]);
            float4 qd = __ldg(&g_Q[d_l]);
            float sch = qs.x + qd.y;
            float scl = qs.z + qd.w;
            eh_l = __expf(-fmaxf(sch, 0.2f * sch));
            el_l = __expf(-fmaxf(scl, 0.2f * scl));
        }
        rsh += eh_l;
        rsl += el_l;
        for (int j = 0; j < cnt; j++) {
            int   dj  = __shfl_sync(0xffffffffu, d_l, j);
            float ehj = __shfl_sync(0xffffffffu, eh_l, j);
            float elj = __shfl_sync(0xffffffffu, el_l, j);
            uint2 raw = __ldg((const uint2*)&g_ZH[(size_t)dj * C2 + lane * 4]);
            float2 f01 = __half22float2(*(__half2*)&raw.x);
            float2 f23 = __half22float2(*(__half2*)&raw.y);
            float ec = hi ? ehj : elj;
            acc.x = fmaf(f01.x, ec, acc.x);
            acc.y = fmaf(f01.y, ec, acc.y);
            acc.z = fmaf(f23.x, ec, acc.z);
            acc.w = fmaf(f23.y, ec, acc.w);
        }
    }
    #pragma unroll
    for (int o = 16; o; o >>= 1) {
        rsh += __shfl_xor_sync(0xffffffffu, rsh, o);
        rsl += __shfl_xor_sync(0xffffffffu, rsl, o);
    }
    float theta = hi ? g_scal[2] : g_scal[3];
    float inv = 1.0f / ((hi ? rsh : rsl) + theta);
    float4 v = make_float4(leaky(acc.x * inv), leaky(acc.y * inv),
                           leaky(acc.z * inv), leaky(acc.w * inv));
    *(float4*)(out + (size_t)gw * C2 + lane * 4) = v;
}

extern "C" void kernel_launch(void* const* d_in, const int* in_sizes, int n_in,
                              void* d_out, int out_size) {
    const float* X    = (const float*)d_in[0];
    const int*   edge = (const int*)d_in[1];
    const float* Wh   = (const float*)d_in[2];
    const float* Wl   = (const float*)d_in[3];
    const float* ah   = (const float*)d_in[4];
    const float* al   = (const float*)d_in[5];
    const float* ch   = (const float*)d_in[6];
    const float* cl   = (const float*)d_in[7];
    float* out = (float*)d_out;

    int N = in_sizes[0] / DIN;
    int E = in_sizes[1] / 2;

    // Side stream + events, created once on the first (non-captured) call.
    static cudaStream_t s2 = nullptr;
    static cudaEvent_t  evFork = nullptr, evJoin = nullptr;
    if (s2 == nullptr) {
        cudaStreamCreateWithFlags(&s2, cudaStreamNonBlocking);
        cudaEventCreateWithFlags(&evFork, cudaEventDisableTiming);
        cudaEventCreateWithFlags(&evJoin, cudaEventDisableTiming);
    }

    // setup (also zeroes g_deg) on the main stream
    setup_kernel<<<128, 256>>>(Wh, Wl, ah, al, ch, cl);

    // fork: CSR build on side stream, GEMM on main stream (independent dataflows)
    cudaEventRecord(evFork, 0);
    cudaStreamWaitEvent(s2, evFork, 0);

    count_kernel<<<2048, 256, 0, s2>>>(edge, E);
    scan_kernel<<<1, 1024, 0, s2>>>(N);
    fill_kernel<<<2048, 256, 0, s2>>>(edge, edge + E, E);
    cudaEventRecord(evJoin, s2);

    gemm_tc_kernel<<<(N + 127) / 128, 256>>>(X, N);

    // join: agg needs both CSR and H/Q
    cudaStreamWaitEvent(0, evJoin, 0);
    agg_kernel<<<(N * 32 + 255) / 256, 256>>>(out, N);
}

// round 15
// speedup vs baseline: 1.9528x; 1.1017x over previous
#include <cuda_runtime.h>
#include <cuda_bf16.h>
#include <cuda_fp16.h>
#include <cstdint>

#define NMAX 100000
#define EMAX 1600000
#define DIN  256
#define F    64
#define C2   128

// ---------------- scratch (device globals: allocation-free rule) ----------------
__device__ __align__(16) __half g_ZH[(size_t)NMAX * C2];   // H = leaky(X@W), fp16 rows
__device__ float4 g_Q[NMAX];                 // per-node score scalars, pre-scaled by 1/||a||
__device__ float  g_w[6 * F];                // folded a-vector combos
__device__ float  g_scal[4];                 // inv_norm_high, inv_norm_low, theta_high, theta_low
__device__ int    g_deg[NMAX + 4];
__device__ int    g_rs[NMAX + 4];            // CSR row start (exclusive prefix of deg)
__device__ int    g_cur[NMAX + 4];           // fill cursors
__device__ int    g_csr[EMAX];               // dst indices grouped by src
// Pre-converted, pre-transposed B = [Wh|Wl]: [128 n][256 k] fp16 image (L2-hot).
__device__ __align__(16) __half g_Bt[128 * 256];

__device__ __forceinline__ float leaky(float x) { return fmaxf(x, 0.2f * x); }

__device__ __forceinline__ uint32_t smem_u32(const void* p) {
    uint32_t a;
    asm("{ .reg .u64 t; cvta.to.shared.u64 t, %1; cvt.u32.u64 %0, t; }" : "=r"(a) : "l"(p));
    return a;
}

#define LDMX4(r0, r1, r2, r3, addr) \
    asm volatile("ldmatrix.sync.aligned.m8n8.x4.shared.b16 {%0,%1,%2,%3}, [%4];" \
                 : "=r"(r0), "=r"(r1), "=r"(r2), "=r"(r3) : "r"(addr))

#define MMA16816F16(d, a, b0, b1) \
    asm volatile("mma.sync.aligned.m16n8k16.row.col.f32.f16.f16.f32 " \
                 "{%0,%1,%2,%3}, {%4,%5,%6,%7}, {%8,%9}, {%0,%1,%2,%3};" \
                 : "+f"((d)[0]), "+f"((d)[1]), "+f"((d)[2]), "+f"((d)[3]) \
                 : "r"((a)[0]), "r"((a)[1]), "r"((a)[2]), "r"((a)[3]), "r"(b0), "r"(b1))

// ---------------- K0: setup (prep scalars/weights + B image + zero deg) ----------------
__global__ void setup_kernel(const float* __restrict__ Wh, const float* __restrict__ Wl,
                             const float* __restrict__ ah, const float* __restrict__ al,
                             const float* __restrict__ ch, const float* __restrict__ cl) {
    int t = threadIdx.x;
    int e = blockIdx.x * 256 + t;        // 0..32767 over 128 blocks

    if (blockIdx.x == 0) {
        __shared__ float sh[256], sl[256];
        float vh = ah[t], vl = al[t];
        sh[t] = vh * vh; sl[t] = vl * vl;
        __syncthreads();
        for (int o = 128; o; o >>= 1) {
            if (t < o) { sh[t] += sh[t + o]; sl[t] += sl[t + o]; }
            __syncthreads();
        }
        if (t == 0) {
            g_scal[0] = 1.0f / sqrtf(sh[0]);
            g_scal[1] = 1.0f / sqrtf(sl[0]);
            float c = ch[0];
            g_scal[2] = (fminf(fmaxf(c + 3.0f, 0.0f), 6.0f) / 3.0f + 1e-6f) * 0.5f;
            c = cl[0];
            g_scal[3] = (fminf(fmaxf(c + 3.0f, 0.0f), 6.0f) / 3.0f + 1e-6f) * 0.5f;
        }
        if (t < F) {
            g_w[t]         = ah[t]     + ah[2*F+t] + ah[3*F+t];   // wh1
            g_w[F + t]     = ah[F+t]   + ah[2*F+t] - ah[3*F+t];   // wh2
            g_w[2*F + t]   = al[t];                                // vl1
            g_w[3*F + t]   = al[F+t];                              // vl2
            g_w[4*F + t]   = al[2*F+t] + al[3*F+t];                // vl3
            g_w[5*F + t]   = al[2*F+t] - al[3*F+t];                // vl4
        }
    }

    {
        int n = e >> 8;
        int k = e & 255;
        float v = (n < 64) ? Wh[(size_t)k * F + n] : Wl[(size_t)k * F + (n - 64)];
        g_Bt[e] = __float2half_rn(v);
    }

    for (int i = e; i < NMAX + 4; i += 32768) g_deg[i] = 0;
}

// ---------------- CSR build ----------------
__global__ void count_kernel(const int* __restrict__ src, int E) {
    int i = blockIdx.x * blockDim.x + threadIdx.x;
    int stride = gridDim.x * blockDim.x;
    for (int e = i; e < E; e += stride) atomicAdd(&g_deg[__ldg(src + e)], 1);
}

__global__ void scan_kernel(int N) {
    __shared__ int part[1024];
    int t = threadIdx.x;
    int Cc = (((N + 1023) >> 10) + 3) & ~3;
    int base = t * Cc;
    int s = 0;
    for (int i = 0; i < Cc; i += 4) {
        int idx = base + i;
        if (idx < N) {
            int4 v = *(const int4*)&g_deg[idx];   // padded; beyond-N entries are 0
            s += v.x + v.y + v.z + v.w;
        }
    }
    part[t] = s;
    __syncthreads();
    for (int o = 1; o < 1024; o <<= 1) {
        int v = (t >= o) ? part[t - o] : 0;
        __syncthreads();
        part[t] += v;
        __syncthreads();
    }
    int run = part[t] - s;
    for (int i = 0; i < Cc; i += 4) {
        int idx = base + i;
        if (idx < N) {
            int4 v = *(const int4*)&g_deg[idx];
            int4 r;
            r.x = run;
            r.y = r.x + v.x;
            r.z = r.y + v.y;
            r.w = r.z + v.z;
            run = r.w + v.w;
            *(int4*)&g_rs[idx]  = r;
            *(int4*)&g_cur[idx] = r;
        }
    }
}

__global__ void fill_kernel(const int* __restrict__ src, const int* __restrict__ dst, int E) {
    int i = blockIdx.x * blockDim.x + threadIdx.x;
    int stride = gridDim.x * blockDim.x;
    for (int e = i; e < E; e += stride) {
        int s = __ldg(src + e);
        int pos = atomicAdd(&g_cur[s], 1);
        g_csr[pos] = __ldg(dst + e);
    }
}

// ---------------- K1: single-pass fp16 HMMA GEMM, 2 CTAs/SM + fused leaky + Q, fp16 H out ----------------
#define ASTRIDE 40   // fp16 elements per smem row (32 + 8 pad)

__global__ void __launch_bounds__(256, 2) gemm_tc_kernel(const float* __restrict__ X, int N) {
    __shared__ __half As[128 * ASTRIDE];
    __shared__ __half Bs[128 * ASTRIDE];
    __shared__ float sW[6 * F];        // folded weight vectors
    __shared__ float sQA[128][4];      // high-slab partial dots per row
    __shared__ float sQB[128][2];      // low-slab partial dots per row

    int tid  = threadIdx.x;
    int wid  = tid >> 5;
    int lane = tid & 31;
    int brow = blockIdx.x * 128;
    int warp_m = wid & 3;
    int warp_n = wid >> 2;

    if (tid < 128) {
        sW[tid]       = g_w[tid];
        sW[tid + 128] = g_w[tid + 128];
        sW[tid + 256] = g_w[tid + 256];
    }

    float acc[2][8][4];
    #pragma unroll
    for (int mi = 0; mi < 2; mi++)
        #pragma unroll
        for (int ni = 0; ni < 8; ni++)
            #pragma unroll
            for (int q = 0; q < 4; q++) acc[mi][ni][q] = 0.f;

    uint32_t sbA = smem_u32(As);
    uint32_t sbB = smem_u32(Bs);

    int a_r = lane & 15, a_c = (lane >> 4) << 3;
    int b_r = lane & 7;
    int b_n = ((lane >> 4) & 1) << 3;
    int b_k = ((lane >> 3) & 1) << 3;

    int arow[4], ac4[4];
    #pragma unroll
    for (int i = 0; i < 4; i++) {
        int idx = tid + 256 * i;
        arow[i] = idx >> 3;
        ac4[i]  = (idx & 7) << 2;
    }
    int bn[2], bk[2];
    #pragma unroll
    for (int i = 0; i < 2; i++) {
        int idx = tid + 256 * i;
        bn[i] = idx >> 2;
        bk[i] = (idx & 3) << 3;
    }

    for (int chunk = 0; chunk < 8; chunk++) {
        int k0 = chunk * 32;
        __syncthreads();   // smem free (prev MMA done)
        // A: load X fp32, convert fp16 -> smem (latency hidden by 2-CTA overlap)
        #pragma unroll
        for (int i = 0; i < 4; i++) {
            int grow = brow + arow[i];
            float4 v = (grow < N) ? *(const float4*)(X + (size_t)grow * DIN + k0 + ac4[i])
                                  : make_float4(0.f, 0.f, 0.f, 0.f);
            __half2 p0 = __floats2half2_rn(v.x, v.y);
            __half2 p1 = __floats2half2_rn(v.z, v.w);
            int o = arow[i] * ASTRIDE + ac4[i];
            uint2 st;
            st.x = *(uint32_t*)&p0;
            st.y = *(uint32_t*)&p1;
            *(uint2*)&As[o] = st;    // 8 B aligned: rows are 80 B, ac4*2 multiple of 8
        }
        // B: copy pre-converted image (L2-hot); 512 uint4 slots over 2 iters
        #pragma unroll
        for (int i = 0; i < 2; i++) {
            uint4 vb = *(const uint4*)(g_Bt + (size_t)bn[i] * 256 + k0 + bk[i]);
            *(uint4*)&Bs[bn[i] * ASTRIDE + bk[i]] = vb;
        }
        __syncthreads();   // smem ready

        #pragma unroll
        for (int ks = 0; ks < 2; ks++) {
            int k16 = ks * 16;
            uint32_t af[2][4];
            #pragma unroll
            for (int mi = 0; mi < 2; mi++) {
                uint32_t aoff = ((warp_m * 32 + mi * 16 + a_r) * ASTRIDE + k16 + a_c) * 2;
                LDMX4(af[mi][0], af[mi][1], af[mi][2], af[mi][3], sbA + aoff);
            }
            #pragma unroll
            for (int np = 0; np < 4; np++) {
                uint32_t boff = ((warp_n * 64 + np * 16 + b_n + b_r) * ASTRIDE + k16 + b_k) * 2;
                uint32_t bf[4];
                LDMX4(bf[0], bf[1], bf[2], bf[3], sbB + boff);
                #pragma unroll
                for (int mi = 0; mi < 2; mi++) {
                    #pragma unroll
                    for (int h = 0; h < 2; h++) {
                        float* d = acc[mi][np * 2 + h];
                        MMA16816F16(d, af[mi], bf[2 * h], bf[2 * h + 1]);
                    }
                }
            }
        }
    }

    // --- Epilogue: leaky + store H (fp16) + fused per-row score dots ---
    __syncthreads();
    int rq   = lane >> 2;
    int col0 = warp_n * 64 + ((lane & 3) << 1);
    int cl0  = (lane & 3) << 1;
    float dots[2][2][4];
    #pragma unroll
    for (int mi = 0; mi < 2; mi++)
        #pragma unroll
        for (int rh = 0; rh < 2; rh++)
            #pragma unroll
            for (int q = 0; q < 4; q++) dots[mi][rh][q] = 0.f;

    #pragma unroll
    for (int mi = 0; mi < 2; mi++) {
        int r0 = brow + warp_m * 32 + mi * 16 + rq;
        #pragma unroll
        for (int ni = 0; ni < 8; ni++) {
            int c  = col0 + ni * 8;
            int lc = cl0 + ni * 8;
            float* d = acc[mi][ni];
            float h0 = leaky(d[0]), h1 = leaky(d[1]);
            float h2 = leaky(d[2]), h3 = leaky(d[3]);
            if (r0 < N)
                *(__half2*)&g_ZH[(size_t)r0 * C2 + c] = __floats2half2_rn(h0, h1);
            if (r0 + 8 < N)
                *(__half2*)&g_ZH[(size_t)(r0 + 8) * C2 + c] = __floats2half2_rn(h2, h3);
            if (warp_n == 0) {
                #pragma unroll
                for (int q = 0; q < 4; q++) {
                    float wa = sW[q * F + lc], wb = sW[q * F + lc + 1];
                    dots[mi][0][q] = fmaf(h0, wa, fmaf(h1, wb, dots[mi][0][q]));
                    dots[mi][1][q] = fmaf(h2, wa, fmaf(h3, wb, dots[mi][1][q]));
                }
            } else {
                #pragma unroll
                for (int q = 0; q < 2; q++) {
                    float wa = sW[(4 + q) * F + lc], wb = sW[(4 + q) * F + lc + 1];
                    dots[mi][0][q] = fmaf(h0, wa, fmaf(h1, wb, dots[mi][0][q]));
                    dots[mi][1][q] = fmaf(h2, wa, fmaf(h3, wb, dots[mi][1][q]));
                }
            }
        }
    }
    #pragma unroll
    for (int mi = 0; mi < 2; mi++)
        #pragma unroll
        for (int rh = 0; rh < 2; rh++)
            #pragma unroll
            for (int q = 0; q < 4; q++) {
                float v = dots[mi][rh][q];
                v += __shfl_xor_sync(0xffffffffu, v, 1);
                v += __shfl_xor_sync(0xffffffffu, v, 2);
                dots[mi][rh][q] = v;
            }
    if ((lane & 3) == 0) {
        #pragma unroll
        for (int mi = 0; mi < 2; mi++)
            #pragma unroll
            for (int rh = 0; rh < 2; rh++) {
                int row = warp_m * 32 + mi * 16 + rh * 8 + rq;
                if (warp_n == 0) {
                    sQA[row][0] = dots[mi][rh][0];
                    sQA[row][1] = dots[mi][rh][1];
                    sQA[row][2] = dots[mi][rh][2];
                    sQA[row][3] = dots[mi][rh][3];
                } else {
                    sQB[row][0] = dots[mi][rh][0];
                    sQB[row][1] = dots[mi][rh][1];
                }
            }
    }
    __syncthreads();
    if (tid < 128) {
        int grow = brow + tid;
        if (grow < N) {
            float inh = g_scal[0], inl = g_scal[1];
            g_Q[grow] = make_float4(sQA[tid][0] * inh,
                                    sQA[tid][1] * inh,
                                    (sQA[tid][2] + sQB[tid][0]) * inl,
                                    (sQA[tid][3] + sQB[tid][1]) * inl);
        }
    }
}

// ---------------- K3: CSR aggregation, warp per node, edge-parallel two-phase, fp16 H ----------------
__global__ void __launch_bounds__(256) agg_kernel(float* __restrict__ out, int N) {
    int gw   = (int)(((size_t)blockIdx.x * blockDim.x + threadIdx.x) >> 5);
    int lane = threadIdx.x & 31;
    if (gw >= N) return;
    float4 qs = g_Q[gw];
    int start = g_rs[gw];
    int end   = start + g_deg[gw];
    bool hi = lane < 16;
    float4 acc = make_float4(0.f, 0.f, 0.f, 0.f);
    float rsh = 0.f, rsl = 0.f;
    for (int base = start; base < end; base += 32) {
        int cnt = min(32, end - base);
        int   d_l  = 0;
        float eh_l = 0.f, el_l = 0.f;
        if (lane < cnt) {
            d_l = __ldg(&g_csr[base + lane]);
            float4 qd = __ldg(&g_Q[d_l]);
            float sch = qs.x + qd.y;
            float scl = qs.z + qd.w;
            eh_l = __expf(-fmaxf(sch, 0.2f * sch));
            el_l = __expf(-fmaxf(scl, 0.2f * scl));
        }
        rsh += eh_l;
        rsl += el_l;
        for (int j = 0; j < cnt; j++) {
            int   dj  = __shfl_sync(0xffffffffu, d_l, j);
            float ehj = __shfl_sync(0xffffffffu, eh_l, j);
            float elj = __shfl_sync(0xffffffffu, el_l, j);
            uint2 raw = __ldg((const uint2*)&g_ZH[(size_t)dj * C2 + lane * 4]);
            float2 f01 = __half22float2(*(__half2*)&raw.x);
            float2 f23 = __half22float2(*(__half2*)&raw.y);
            float ec = hi ? ehj : elj;
            acc.x = fmaf(f01.x, ec, acc.x);
            acc.y = fmaf(f01.y, ec, acc.y);
            acc.z = fmaf(f23.x, ec, acc.z);
            acc.w = fmaf(f23.y, ec, acc.w);
        }
    }
    #pragma unroll
    for (int o = 16; o; o >>= 1) {
        rsh += __shfl_xor_sync(0xffffffffu, rsh, o);
        rsl += __shfl_xor_sync(0xffffffffu, rsl, o);
    }
    float theta = hi ? g_scal[2] : g_scal[3];
    float inv = 1.0f / ((hi ? rsh : rsl) + theta);
    float4 v = make_float4(leaky(acc.x * inv), leaky(acc.y * inv),
                           leaky(acc.z * inv), leaky(acc.w * inv));
    *(float4*)(out + (size_t)gw * C2 + lane * 4) = v;
}

extern "C" void kernel_launch(void* const* d_in, const int* in_sizes, int n_in,
                              void* d_out, int out_size) {
    const float* X    = (const float*)d_in[0];
    const int*   edge = (const int*)d_in[1];
    const float* Wh   = (const float*)d_in[2];
    const float* Wl   = (const float*)d_in[3];
    const float* ah   = (const float*)d_in[4];
    const float* al   = (const float*)d_in[5];
    const float* ch   = (const float*)d_in[6];
    const float* cl   = (const float*)d_in[7];
    float* out = (float*)d_out;

    int N = in_sizes[0] / DIN;
    int E = in_sizes[1] / 2;

    // Side stream + events, created once on the first (non-captured) call.
    static cudaStream_t s2 = nullptr;
    static cudaEvent_t  evFork = nullptr, evJoin = nullptr;
    if (s2 == nullptr) {
        cudaStreamCreateWithFlags(&s2, cudaStreamNonBlocking);
        cudaEventCreateWithFlags(&evFork, cudaEventDisableTiming);
        cudaEventCreateWithFlags(&evJoin, cudaEventDisableTiming);
    }

    // setup (also zeroes g_deg) on the main stream
    setup_kernel<<<128, 256>>>(Wh, Wl, ah, al, ch, cl);

    // fork: CSR build on side stream, GEMM on main stream (independent dataflows)
    cudaEventRecord(evFork, 0);
    cudaStreamWaitEvent(s2, evFork, 0);

    count_kernel<<<2048, 256, 0, s2>>>(edge, E);
    scan_kernel<<<1, 1024, 0, s2>>>(N);
    fill_kernel<<<2048, 256, 0, s2>>>(edge, edge + E, E);
    cudaEventRecord(evJoin, s2);

    gemm_tc_kernel<<<(N + 127) / 128, 256>>>(X, N);

    // join: agg needs both CSR and H/Q
    cudaStreamWaitEvent(0, evJoin, 0);
    agg_kernel<<<(N * 32 + 255) / 256, 256>>>(out, N);
}